// round 11
// baseline (speedup 1.0000x reference)
#include <cuda_runtime.h>
#include <cuda.h>
#include <cuda_bf16.h>
#include <math.h>
#include <stdint.h>

// Problem dims (fixed by setup_inputs)
#define T_TOK 2048
#define DIM   2048
#define NEXP  16
#define IDIM  1024
#define SIDIM 2048
#define TOPK  4

#define BM 128
#define MAXROWS (T_TOK*TOPK + NEXP*BM)   // 10240
#define MAXTILES (MAXROWS/BM)            // 80

// ======================= scratch (device globals) =======================
__device__ __nv_bfloat16 g_xh[(size_t)T_TOK*DIM];
__device__ __nv_bfloat16 g_xl[(size_t)T_TOK*DIM];
__device__ __nv_bfloat16 g_agh[(size_t)MAXROWS*DIM];
__device__ __nv_bfloat16 g_agl[(size_t)MAXROWS*DIM];
__device__ __nv_bfloat16 g_wguT_h[(size_t)NEXP*2*IDIM*DIM];   // interleaved gate/up rows
__device__ __nv_bfloat16 g_wguT_l[(size_t)NEXP*2*IDIM*DIM];
__device__ __nv_bfloat16 g_wdT_h[(size_t)NEXP*DIM*IDIM];
__device__ __nv_bfloat16 g_wdT_l[(size_t)NEXP*DIM*IDIM];
__device__ __nv_bfloat16 g_wsguT_h[(size_t)2*SIDIM*DIM];      // interleaved
__device__ __nv_bfloat16 g_wsguT_l[(size_t)2*SIDIM*DIM];
__device__ __nv_bfloat16 g_wsdT_h[(size_t)DIM*SIDIM];
__device__ __nv_bfloat16 g_wsdT_l[(size_t)DIM*SIDIM];
__device__ __nv_bfloat16 g_hbh[(size_t)MAXROWS*IDIM];
__device__ __nv_bfloat16 g_hbl[(size_t)MAXROWS*IDIM];
__device__ __nv_bfloat16 g_hsh_h[(size_t)T_TOK*SIDIM];
__device__ __nv_bfloat16 g_hsh_l[(size_t)T_TOK*SIDIM];
__device__ float g_eout[(size_t)MAXROWS*DIM];

__device__ int   g_topidx[T_TOK*TOPK];
__device__ float g_topw[T_TOK*TOPK];
__device__ int   g_counts[NEXP];
__device__ int   g_fill[NEXP];
__device__ int   g_offsets[NEXP];
__device__ int   g_tile_expert[MAXTILES];
__device__ int   g_rowtok[MAXROWS];
__device__ int   g_posmap[T_TOK*TOPK];

__device__ __forceinline__ float4 ld4(const float* p) {
    return *reinterpret_cast<const float4*>(p);
}

__device__ __forceinline__ uint32_t smem_to_u32(const void* smem_ptr) {
    uint32_t addr;
    asm("{ .reg .u64 tmp; cvta.to.shared.u64 tmp, %1; cvt.u32.u64 %0, tmp; }"
        : "=r"(addr) : "l"(smem_ptr));
    return addr;
}

// ======================= router / scheduling =======================
__global__ void router_kernel(const float* __restrict__ x,
                              const float* __restrict__ gw,
                              const float* __restrict__ gb)
{
    __shared__ float sx[DIM];
    __shared__ float slog[NEXP];
    const int t   = blockIdx.x;
    const int tid = threadIdx.x;           // 512 threads

    *reinterpret_cast<float4*>(&sx[tid*4]) = ld4(x + (long long)t*DIM + tid*4);
    __syncthreads();

    const int w = tid >> 5, lane = tid & 31;
    const float* gwr = gw + w*DIM;
    float s = 0.f;
    for (int i = lane*4; i < DIM; i += 32*4) {
        float4 xv = *reinterpret_cast<float4*>(&sx[i]);
        float4 gv = ld4(gwr + i);
        s += xv.x*gv.x + xv.y*gv.y + xv.z*gv.z + xv.w*gv.w;
    }
    #pragma unroll
    for (int o = 16; o; o >>= 1) s += __shfl_down_sync(0xffffffffu, s, o);
    if (lane == 0) slog[w] = s;
    __syncthreads();

    if (tid == 0) {
        float p[NEXP], mx = -1e30f;
        #pragma unroll
        for (int e = 0; e < NEXP; e++) mx = fmaxf(mx, slog[e]);
        float sum = 0.f;
        #pragma unroll
        for (int e = 0; e < NEXP; e++) { p[e] = expf(slog[e] - mx); sum += p[e]; }
        const float inv = 1.f / sum;
        float score[NEXP];
        #pragma unroll
        for (int e = 0; e < NEXP; e++) { p[e] *= inv; score[e] = p[e] + gb[e]; }

        int sel[TOPK]; float wsum = 0.f;
        #pragma unroll
        for (int k = 0; k < TOPK; k++) {
            int best = 0; float bv = -1e30f;
            #pragma unroll
            for (int e = 0; e < NEXP; e++)
                if (score[e] > bv) { bv = score[e]; best = e; }
            sel[k] = best; score[best] = -1e31f; wsum += p[best];
        }
        const float invw = 1.f / wsum;
        #pragma unroll
        for (int k = 0; k < TOPK; k++) {
            g_topidx[t*TOPK + k] = sel[k];
            g_topw [t*TOPK + k] = p[sel[k]] * invw;
            atomicAdd(&g_counts[sel[k]], 1);
        }
    }
}

__global__ void zero_meta()
{
    int i = threadIdx.x;
    if (i < NEXP) { g_counts[i] = 0; g_fill[i] = 0; }
}

__global__ void sched_kernel()
{
    const int tid = threadIdx.x;
    if (tid == 0) {
        int base = 0;
        for (int e = 0; e < NEXP; e++) {
            g_offsets[e] = base;
            int nt = (g_counts[e] + BM - 1) / BM;
            int t0 = base / BM;
            for (int j = 0; j < nt; j++) g_tile_expert[t0 + j] = e;
            base += nt * BM;
        }
        for (int tl = base / BM; tl < MAXTILES; tl++) g_tile_expert[tl] = -1;
    }
    for (int i = tid; i < MAXROWS; i += blockDim.x) g_rowtok[i] = -1;
}

__global__ void scatter_kernel()
{
    const int p = blockIdx.x * blockDim.x + threadIdx.x;
    if (p >= T_TOK*TOPK) return;
    const int e = g_topidx[p];
    const int r = atomicAdd(&g_fill[e], 1);
    const int pos = g_offsets[e] + r;
    g_rowtok[pos] = p >> 2;
    g_posmap[p]   = pos;
}

// ======================= conversion kernels =======================
__device__ __forceinline__ void split_bf16(float v, __nv_bfloat16& hi, __nv_bfloat16& lo) {
    hi = __float2bfloat16(v);
    lo = __float2bfloat16(v - __bfloat162float(hi));
}

__global__ void convert_x_kernel(const float* __restrict__ src,
                                 __nv_bfloat16* __restrict__ dh,
                                 __nv_bfloat16* __restrict__ dl, long long n4)
{
    long long p = (long long)blockIdx.x * blockDim.x + threadIdx.x;
    if (p >= n4) return;
    float4 v = ld4(src + p*4);
    union { __nv_bfloat16 b[4]; unsigned long long u; } H, L;
    split_bf16(v.x, H.b[0], L.b[0]);
    split_bf16(v.y, H.b[1], L.b[1]);
    split_bf16(v.z, H.b[2], L.b[2]);
    split_bf16(v.w, H.b[3], L.b[3]);
    *reinterpret_cast<unsigned long long*>(dh + p*4) = H.u;
    *reinterpret_cast<unsigned long long*>(dl + p*4) = L.u;
}

__global__ void gather_rows(const __nv_bfloat16* __restrict__ xh,
                            const __nv_bfloat16* __restrict__ xl,
                            __nv_bfloat16* __restrict__ agh,
                            __nv_bfloat16* __restrict__ agl)
{
    const int row = blockIdx.x;
    const int tid = threadIdx.x;   // 256 threads; DIM*2B = 4KB = 256x16B
    const int tok = g_rowtok[row];
    uint4* dh = reinterpret_cast<uint4*>(agh + (long long)row*DIM);
    uint4* dl = reinterpret_cast<uint4*>(agl + (long long)row*DIM);
    if (tok >= 0) {
        const uint4* sh = reinterpret_cast<const uint4*>(xh + (long long)tok*DIM);
        const uint4* sl = reinterpret_cast<const uint4*>(xl + (long long)tok*DIM);
        dh[tid] = sh[tid];
        dl[tid] = sl[tid];
    } else {
        uint4 z = make_uint4(0,0,0,0);
        dh[tid] = z; dl[tid] = z;
    }
}

// fp32 src [E][R][C] -> bf16 hi/lo dst [E][C][R]  (transpose + split)
// glu_half H != 0: remap dest row so each 128-row group = 64 gate rows + 64 up rows
// covering the same 64 output columns (enables fused swiglu epilogue).
__global__ void transpose_convert(const float* __restrict__ src,
                                  __nv_bfloat16* __restrict__ dh,
                                  __nv_bfloat16* __restrict__ dl,
                                  int R, int C, int glu_half)
{
    __shared__ float t[32][33];
    const int e  = blockIdx.z;
    const int c0 = blockIdx.x * 32;
    const int r0 = blockIdx.y * 32;
    const int tx = threadIdx.x, ty = threadIdx.y;   // (32, 8)
    const float* s = src + (long long)e*R*C;
    #pragma unroll
    for (int j = 0; j < 32; j += 8)
        t[ty+j][tx] = s[(long long)(r0+ty+j)*C + c0+tx];
    __syncthreads();
    __nv_bfloat16* oh = dh + (long long)e*C*R;
    __nv_bfloat16* ol = dl + (long long)e*C*R;
    #pragma unroll
    for (int j = 0; j < 32; j += 8) {
        float v = t[tx][ty+j];
        __nv_bfloat16 hi, lo; split_bf16(v, hi, lo);
        int c = c0 + ty + j;
        long long dr;
        if (glu_half == 0) dr = c;
        else if (c < glu_half) dr = (long long)(c >> 6)*128 + (c & 63);
        else { int cc = c - glu_half; dr = (long long)(cc >> 6)*128 + 64 + (cc & 63); }
        long long di = dr*R + r0+tx;
        oh[di] = hi; ol[di] = lo;
    }
}

// ======================= mma.sync GEMM core =======================
// C tile 128x128. A [M,K] row-major, B [N,K] row-major (both K-contig), bf16 hi/lo.
// bf16x3 split: C = Ah*Bh + Ah*Bl + Al*Bh  (fp32 register accum)
// 256 threads = 8 warps (2 M x 4 N); warp tile 64x32; mma m16n8k16; k-step 16.
// Stage = 16KB; 3 stages = 48KB static. Swizzle c ^ ((r>>1)&3) over 16B chunks.

#define SWZ64(r, c) ((uint32_t)(r)*64u + ((uint32_t)(((c) ^ (((r)>>1)&3))) << 4))
#define SB_OFF 8192
#define STG16  16384

__device__ __forceinline__ void cp16(uint32_t d, const void* s) {
    asm volatile("cp.async.cg.shared.global [%0], [%1], 16;\n" :: "r"(d), "l"(s));
}
__device__ __forceinline__ void ldm4(uint32_t* r, uint32_t a) {
    asm volatile("ldmatrix.sync.aligned.m8n8.x4.shared.b16 {%0,%1,%2,%3}, [%4];\n"
        : "=r"(r[0]), "=r"(r[1]), "=r"(r[2]), "=r"(r[3]) : "r"(a));
}
__device__ __forceinline__ void mma16816(float* c, const uint32_t* a, uint32_t b0, uint32_t b1) {
    asm volatile("mma.sync.aligned.m16n8k16.row.col.f32.bf16.bf16.f32 "
        "{%0,%1,%2,%3}, {%4,%5,%6,%7}, {%8,%9}, {%0,%1,%2,%3};\n"
        : "+f"(c[0]), "+f"(c[1]), "+f"(c[2]), "+f"(c[3])
        : "r"(a[0]), "r"(a[1]), "r"(a[2]), "r"(a[3]), "r"(b0), "r"(b1));
}

__device__ __forceinline__ void load_stage(uint32_t st,
    const __nv_bfloat16* __restrict__ Ah, const __nv_bfloat16* __restrict__ Al,
    const __nv_bfloat16* __restrict__ Bh, const __nv_bfloat16* __restrict__ Bl,
    int am0, int bn0, int ldk, int k0, int tid)
{
    const int row = tid >> 1;          // 0..127
    const int cb  = tid & 1;
    const size_t ga = (size_t)(am0+row)*ldk + k0 + cb*8;
    const size_t gb = (size_t)(bn0+row)*ldk + k0 + cb*8;
    cp16(st +          SWZ64(row, cb),     Ah + ga);
    cp16(st +          SWZ64(row, 2 + cb), Al + ga);
    cp16(st + SB_OFF + SWZ64(row, cb),     Bh + gb);
    cp16(st + SB_OFF + SWZ64(row, 2 + cb), Bl + gb);
}

__device__ __forceinline__ void gemm_mainloop(uint32_t sb,
    const __nv_bfloat16* __restrict__ Ah, const __nv_bfloat16* __restrict__ Al,
    const __nv_bfloat16* __restrict__ Bh, const __nv_bfloat16* __restrict__ Bl,
    int m0, int brow0, int K, int tid, int lane, int wm, int wn,
    float acc[4][4][4])
{
    const int nk = K / 16;

    load_stage(sb,         Ah, Al, Bh, Bl, m0, brow0, K, 0,  tid);
    asm volatile("cp.async.commit_group;\n");
    load_stage(sb + STG16, Ah, Al, Bh, Bl, m0, brow0, K, 16, tid);
    asm volatile("cp.async.commit_group;\n");

    int s = 0;
    for (int kt = 0; kt < nk; kt++) {
        asm volatile("cp.async.wait_group 1;\n");
        __syncthreads();

        {
            int s2 = s + 2; if (s2 >= 3) s2 -= 3;
            if (kt + 2 < nk)
                load_stage(sb + s2*STG16, Ah, Al, Bh, Bl, m0, brow0, K, (kt+2)*16, tid);
            asm volatile("cp.async.commit_group;\n");
        }

        const uint32_t Ab = sb + s*STG16;

        uint32_t fbh[2][4], fbl[2][4];
        #pragma unroll
        for (int np = 0; np < 2; np++) {
            const int rb = wn*32 + np*16 + (lane & 7) + ((lane >> 4) << 3);
            const int cbh = (lane >> 3) & 1;
            ldm4(fbh[np], Ab + SB_OFF + SWZ64(rb, cbh));
            ldm4(fbl[np], Ab + SB_OFF + SWZ64(rb, 2 + cbh));
        }

        #pragma unroll
        for (int mt = 0; mt < 4; mt++) {
            uint32_t fah[4], fal[4];
            const int ra = wm*64 + mt*16 + (lane & 15);
            const int ca = lane >> 4;
            ldm4(fah, Ab + SWZ64(ra, ca));
            ldm4(fal, Ab + SWZ64(ra, 2 + ca));
            #pragma unroll
            for (int nt = 0; nt < 4; nt++) {
                const int np = nt >> 1, hx = (nt & 1)*2;
                mma16816(acc[mt][nt], fah, fbh[np][hx], fbh[np][hx+1]);
                mma16816(acc[mt][nt], fah, fbl[np][hx], fbl[np][hx+1]);
                mma16816(acc[mt][nt], fal, fbh[np][hx], fbh[np][hx+1]);
            }
        }

        if (++s >= 3) s -= 3;
    }
    asm volatile("cp.async.wait_group 0;\n");
}

// ---------- merged gate_up GEMM with fused SwiGLU epilogue ----------
// grid.x = 1792: [0,1280) routed (16 x-tiles, 80 y), [1280,1792) shared (32 x, 16 y)
// B rows interleaved: tile x rows = 64 gate cols + 64 up cols (same 64 h-columns).
// Epilogue: gate warps (wn<2) stage fp32 acc via smem; up warps compute
// silu(g)*u, split to bf16 hi/lo, write h[128 x 64] directly.
__global__ void __launch_bounds__(256, 2) gemm_gu_fused(
    const __nv_bfloat16* __restrict__ Ah_r, const __nv_bfloat16* __restrict__ Al_r,
    const __nv_bfloat16* __restrict__ Bh_r, const __nv_bfloat16* __restrict__ Bl_r,
    __nv_bfloat16* __restrict__ Ch_r, __nv_bfloat16* __restrict__ Cl_r,
    const __nv_bfloat16* __restrict__ Ah_s, const __nv_bfloat16* __restrict__ Al_s,
    const __nv_bfloat16* __restrict__ Bh_s, const __nv_bfloat16* __restrict__ Bl_s,
    __nv_bfloat16* __restrict__ Ch_s, __nv_bfloat16* __restrict__ Cl_s,
    const int* __restrict__ tile_expert)
{
    __shared__ char smem[3*STG16];     // 48KB; reused as fp32 gate[128][65] in epilogue
    const uint32_t sb = smem_to_u32(smem);

    const __nv_bfloat16 *Ah, *Al, *Bh, *Bl;
    __nv_bfloat16 *Ch, *Cl;
    int m0, brow0, ldh, hcol0;
    int bid = blockIdx.x;
    if (bid < 1280) {
        const int bx = bid & 15, by = bid >> 4;
        const int e = tile_expert[by];
        if (e < 0) return;
        m0 = by*128; hcol0 = bx*64;
        brow0 = e*(2*IDIM) + bx*128;
        Ah = Ah_r; Al = Al_r; Bh = Bh_r; Bl = Bl_r; Ch = Ch_r; Cl = Cl_r;
        ldh = IDIM;
    } else {
        bid -= 1280;
        const int bx = bid & 31, by = bid >> 5;
        m0 = by*128; hcol0 = bx*64;
        brow0 = bx*128;
        Ah = Ah_s; Al = Al_s; Bh = Bh_s; Bl = Bl_s; Ch = Ch_s; Cl = Cl_s;
        ldh = SIDIM;
    }

    const int tid = threadIdx.x, lane = tid & 31, wid = tid >> 5;
    const int wm = wid & 1, wn = wid >> 1;

    float acc[4][4][4];
    #pragma unroll
    for (int a = 0; a < 4; a++)
        #pragma unroll
        for (int b = 0; b < 4; b++)
            #pragma unroll
            for (int c = 0; c < 4; c++) acc[a][b][c] = 0.f;

    gemm_mainloop(sb, Ah, Al, Bh, Bl, m0, brow0, DIM, tid, lane, wm, wn, acc);

    // ---- fused SwiGLU epilogue ----
    float* gs = reinterpret_cast<float*>(smem);   // [128][65] fp32 = 33280 B
    __syncthreads();                               // smem repurpose barrier

    if (wn < 2) {
        // gate warps: tile cols 0..63 -> stage to smem
        #pragma unroll
        for (int mt = 0; mt < 4; mt++)
            #pragma unroll
            for (int nt = 0; nt < 4; nt++) {
                const int r = wm*64 + mt*16 + (lane >> 2);
                const int c = wn*32 + nt*8 + (lane & 3)*2;
                gs[r*65 + c]       = acc[mt][nt][0];
                gs[r*65 + c + 1]   = acc[mt][nt][1];
                gs[(r+8)*65 + c]   = acc[mt][nt][2];
                gs[(r+8)*65 + c+1] = acc[mt][nt][3];
            }
    }
    __syncthreads();

    if (wn >= 2) {
        // up warps: tile cols 64..127 -> h cols 0..63
        #pragma unroll
        for (int mt = 0; mt < 4; mt++)
            #pragma unroll
            for (int nt = 0; nt < 4; nt++) {
                const int r = wm*64 + mt*16 + (lane >> 2);
                const int j = (wn-2)*32 + nt*8 + (lane & 3)*2;
                #pragma unroll
                for (int half = 0; half < 2; half++) {
                    const int rr = r + half*8;
                    const float g0 = gs[rr*65 + j];
                    const float g1 = gs[rr*65 + j + 1];
                    const float u0 = acc[mt][nt][half*2];
                    const float u1 = acc[mt][nt][half*2 + 1];
                    const float h0 = (g0 / (1.f + expf(-g0))) * u0;
                    const float h1 = (g1 / (1.f + expf(-g1))) * u1;
                    union { __nv_bfloat16 b[2]; uint32_t u; } H, L;
                    split_bf16(h0, H.b[0], L.b[0]);
                    split_bf16(h1, H.b[1], L.b[1]);
                    const long long off = (long long)(m0 + rr)*ldh + hcol0 + j;
                    *reinterpret_cast<uint32_t*>(Ch + off) = H.u;
                    *reinterpret_cast<uint32_t*>(Cl + off) = L.u;
                }
            }
    }
}

// ---------- merged down GEMM (fp32 epilogue) ----------
// grid.x = 1536: [0,1280) routed (16 x, 80 y, K=IDIM), [1280,1536) shared (16 x, 16 y, K=SIDIM)
__global__ void __launch_bounds__(256, 2) gemm_down_merged(
    const __nv_bfloat16* __restrict__ Ah_r, const __nv_bfloat16* __restrict__ Al_r,
    const __nv_bfloat16* __restrict__ Bh_r, const __nv_bfloat16* __restrict__ Bl_r,
    float* __restrict__ C_r,
    const __nv_bfloat16* __restrict__ Ah_s, const __nv_bfloat16* __restrict__ Al_s,
    const __nv_bfloat16* __restrict__ Bh_s, const __nv_bfloat16* __restrict__ Bl_s,
    float* __restrict__ C_s,
    const int* __restrict__ tile_expert)
{
    __shared__ char smem[3*STG16];
    const uint32_t sb = smem_to_u32(smem);

    const __nv_bfloat16 *Ah, *Al, *Bh, *Bl;
    float* C;
    int m0, n0, brow0, K;
    int bid = blockIdx.x;
    if (bid < 1280) {
        const int bx = bid & 15, by = bid >> 4;
        const int e = tile_expert[by];
        if (e < 0) return;
        m0 = by*128; n0 = bx*128;
        brow0 = e*DIM + n0;
        Ah = Ah_r; Al = Al_r; Bh = Bh_r; Bl = Bl_r; C = C_r;
        K = IDIM;
    } else {
        bid -= 1280;
        const int bx = bid & 15, by = bid >> 4;
        m0 = by*128; n0 = bx*128;
        brow0 = n0;
        Ah = Ah_s; Al = Al_s; Bh = Bh_s; Bl = Bl_s; C = C_s;
        K = SIDIM;
    }

    const int tid = threadIdx.x, lane = tid & 31, wid = tid >> 5;
    const int wm = wid & 1, wn = wid >> 1;

    float acc[4][4][4];
    #pragma unroll
    for (int a = 0; a < 4; a++)
        #pragma unroll
        for (int b = 0; b < 4; b++)
            #pragma unroll
            for (int c = 0; c < 4; c++) acc[a][b][c] = 0.f;

    gemm_mainloop(sb, Ah, Al, Bh, Bl, m0, brow0, K, tid, lane, wm, wn, acc);

    const int rbase = m0 + wm*64 + (lane >> 2);
    const int cbase = n0 + wn*32 + (lane & 3)*2;
    #pragma unroll
    for (int mt = 0; mt < 4; mt++)
        #pragma unroll
        for (int nt = 0; nt < 4; nt++) {
            const long long r0 = rbase + mt*16;
            const int c0 = cbase + nt*8;
            *reinterpret_cast<float2*>(C + r0*DIM + c0) =
                make_float2(acc[mt][nt][0], acc[mt][nt][1]);
            *reinterpret_cast<float2*>(C + (r0+8)*DIM + c0) =
                make_float2(acc[mt][nt][2], acc[mt][nt][3]);
        }
}

// ======================= combine =======================
__global__ void combine_kernel(float* __restrict__ out)
{
    const int t = blockIdx.x;
    __shared__ int   spos[TOPK];
    __shared__ float sw[TOPK];
    if (threadIdx.x < TOPK) {
        spos[threadIdx.x] = g_posmap[t*TOPK + threadIdx.x];
        sw[threadIdx.x]   = g_topw [t*TOPK + threadIdx.x];
    }
    __syncthreads();
    for (int d = threadIdx.x*4; d < DIM; d += blockDim.x*4) {
        float4 a = ld4(out + (long long)t*DIM + d);
        #pragma unroll
        for (int k = 0; k < TOPK; k++) {
            const float4 ev = ld4(g_eout + (long long)spos[k]*DIM + d);
            const float wk = sw[k];
            a.x = fmaf(wk, ev.x, a.x); a.y = fmaf(wk, ev.y, a.y);
            a.z = fmaf(wk, ev.z, a.z); a.w = fmaf(wk, ev.w, a.w);
        }
        *reinterpret_cast<float4*>(out + (long long)t*DIM + d) = a;
    }
}

// ======================= host =======================
extern "C" void kernel_launch(void* const* d_in, const int* in_sizes, int n_in,
                              void* d_out, int out_size)
{
    const float* x    = (const float*)d_in[0];
    const float* gw   = (const float*)d_in[1];
    const float* gb   = (const float*)d_in[2];
    const float* wgu  = (const float*)d_in[3];
    const float* wd   = (const float*)d_in[4];
    const float* wsgu = (const float*)d_in[5];
    const float* wsd  = (const float*)d_in[6];
    float* out = (float*)d_out;

    void *xh, *xl, *agh, *agl, *wguTh, *wguTl, *wdTh, *wdTl,
         *wsguTh, *wsguTl, *wsdTh, *wsdTl, *hbh, *hbl,
         *hshh, *hshl, *eout, *tilee;
    cudaGetSymbolAddress(&xh, g_xh);       cudaGetSymbolAddress(&xl, g_xl);
    cudaGetSymbolAddress(&agh, g_agh);     cudaGetSymbolAddress(&agl, g_agl);
    cudaGetSymbolAddress(&wguTh, g_wguT_h);cudaGetSymbolAddress(&wguTl, g_wguT_l);
    cudaGetSymbolAddress(&wdTh, g_wdT_h);  cudaGetSymbolAddress(&wdTl, g_wdT_l);
    cudaGetSymbolAddress(&wsguTh, g_wsguT_h); cudaGetSymbolAddress(&wsguTl, g_wsguT_l);
    cudaGetSymbolAddress(&wsdTh, g_wsdT_h);   cudaGetSymbolAddress(&wsdTl, g_wsdT_l);
    cudaGetSymbolAddress(&hbh, g_hbh);     cudaGetSymbolAddress(&hbl, g_hbl);
    cudaGetSymbolAddress(&hshh, g_hsh_h);  cudaGetSymbolAddress(&hshl, g_hsh_l);
    cudaGetSymbolAddress(&eout, g_eout);
    cudaGetSymbolAddress(&tilee, g_tile_expert);

    // --- routing ---
    zero_meta<<<1, 32>>>();
    router_kernel<<<T_TOK, 512>>>(x, gw, gb);
    sched_kernel<<<1, 256>>>();
    scatter_kernel<<<(T_TOK*TOPK + 255)/256, 256>>>();

    // --- conversions ---
    convert_x_kernel<<<(T_TOK*DIM/4 + 255)/256, 256>>>(
        x, (__nv_bfloat16*)xh, (__nv_bfloat16*)xl, (long long)T_TOK*DIM/4);
    gather_rows<<<MAXROWS, 256>>>((const __nv_bfloat16*)xh, (const __nv_bfloat16*)xl,
                                  (__nv_bfloat16*)agh, (__nv_bfloat16*)agl);
    transpose_convert<<<dim3(2*IDIM/32, DIM/32, NEXP), dim3(32,8)>>>(
        wgu, (__nv_bfloat16*)wguTh, (__nv_bfloat16*)wguTl, DIM, 2*IDIM, IDIM);
    transpose_convert<<<dim3(DIM/32, IDIM/32, NEXP), dim3(32,8)>>>(
        wd, (__nv_bfloat16*)wdTh, (__nv_bfloat16*)wdTl, IDIM, DIM, 0);
    transpose_convert<<<dim3(2*SIDIM/32, DIM/32, 1), dim3(32,8)>>>(
        wsgu, (__nv_bfloat16*)wsguTh, (__nv_bfloat16*)wsguTl, DIM, 2*SIDIM, SIDIM);
    transpose_convert<<<dim3(DIM/32, SIDIM/32, 1), dim3(32,8)>>>(
        wsd, (__nv_bfloat16*)wsdTh, (__nv_bfloat16*)wsdTl, SIDIM, DIM, 0);

    // --- merged gate_up GEMM + fused SwiGLU (routed 1280 + shared 512 CTAs) ---
    gemm_gu_fused<<<1792, 256>>>(
        (const __nv_bfloat16*)agh, (const __nv_bfloat16*)agl,
        (const __nv_bfloat16*)wguTh, (const __nv_bfloat16*)wguTl,
        (__nv_bfloat16*)hbh, (__nv_bfloat16*)hbl,
        (const __nv_bfloat16*)xh, (const __nv_bfloat16*)xl,
        (const __nv_bfloat16*)wsguTh, (const __nv_bfloat16*)wsguTl,
        (__nv_bfloat16*)hshh, (__nv_bfloat16*)hshl,
        (const int*)tilee);

    // --- merged down GEMM (routed 1280 + shared 256 CTAs) ---
    gemm_down_merged<<<1536, 256>>>(
        (const __nv_bfloat16*)hbh, (const __nv_bfloat16*)hbl,
        (const __nv_bfloat16*)wdTh, (const __nv_bfloat16*)wdTl,
        (float*)eout,
        (const __nv_bfloat16*)hshh, (const __nv_bfloat16*)hshl,
        (const __nv_bfloat16*)wsdTh, (const __nv_bfloat16*)wsdTl,
        out,
        (const int*)tilee);

    // --- combine ---
    combine_kernel<<<T_TOK, 256>>>(out);
}

// round 12
// speedup vs baseline: 1.4037x; 1.4037x over previous
#include <cuda_runtime.h>
#include <cuda.h>
#include <cuda_fp16.h>
#include <math.h>
#include <stdint.h>

// Problem dims (fixed by setup_inputs)
#define T_TOK 2048
#define DIM   2048
#define NEXP  16
#define IDIM  1024
#define SIDIM 2048
#define TOPK  4

#define BM 128
#define MAXROWS (T_TOK*TOPK + NEXP*BM)   // 10240
#define MAXTILES (MAXROWS/BM)            // 80

// ======================= scratch (device globals) =======================
__device__ __half g_xh[(size_t)T_TOK*DIM];        // x fp16 hi
__device__ __half g_xl[(size_t)T_TOK*DIM];        // x fp16 lo
__device__ __half g_agh[(size_t)MAXROWS*DIM];     // gathered rows hi
__device__ __half g_agl[(size_t)MAXROWS*DIM];     // gathered rows lo
__device__ __half g_wguT[(size_t)NEXP*2*IDIM*DIM];  // interleaved gate/up rows, fp16
__device__ __half g_wdT[(size_t)NEXP*DIM*IDIM];
__device__ __half g_wsguT[(size_t)2*SIDIM*DIM];     // interleaved
__device__ __half g_wsdT[(size_t)DIM*SIDIM];
__device__ __half g_hbh[(size_t)MAXROWS*IDIM];    // h hi
__device__ __half g_hbl[(size_t)MAXROWS*IDIM];    // h lo
__device__ __half g_hsh_h[(size_t)T_TOK*SIDIM];
__device__ __half g_hsh_l[(size_t)T_TOK*SIDIM];
__device__ float g_eout[(size_t)MAXROWS*DIM];

__device__ int   g_topidx[T_TOK*TOPK];
__device__ float g_topw[T_TOK*TOPK];
__device__ int   g_counts[NEXP];
__device__ int   g_fill[NEXP];
__device__ int   g_offsets[NEXP];
__device__ int   g_tile_expert[MAXTILES];
__device__ int   g_rowtok[MAXROWS];
__device__ int   g_posmap[T_TOK*TOPK];

__device__ __forceinline__ float4 ld4(const float* p) {
    return *reinterpret_cast<const float4*>(p);
}

__device__ __forceinline__ uint32_t smem_to_u32(const void* smem_ptr) {
    uint32_t addr;
    asm("{ .reg .u64 tmp; cvta.to.shared.u64 tmp, %1; cvt.u32.u64 %0, tmp; }"
        : "=r"(addr) : "l"(smem_ptr));
    return addr;
}

// ======================= router / scheduling =======================
__global__ void router_kernel(const float* __restrict__ x,
                              const float* __restrict__ gw,
                              const float* __restrict__ gb)
{
    __shared__ float sx[DIM];
    __shared__ float slog[NEXP];
    const int t   = blockIdx.x;
    const int tid = threadIdx.x;           // 512 threads

    *reinterpret_cast<float4*>(&sx[tid*4]) = ld4(x + (long long)t*DIM + tid*4);
    __syncthreads();

    const int w = tid >> 5, lane = tid & 31;
    const float* gwr = gw + w*DIM;
    float s = 0.f;
    for (int i = lane*4; i < DIM; i += 32*4) {
        float4 xv = *reinterpret_cast<float4*>(&sx[i]);
        float4 gv = ld4(gwr + i);
        s += xv.x*gv.x + xv.y*gv.y + xv.z*gv.z + xv.w*gv.w;
    }
    #pragma unroll
    for (int o = 16; o; o >>= 1) s += __shfl_down_sync(0xffffffffu, s, o);
    if (lane == 0) slog[w] = s;
    __syncthreads();

    if (tid == 0) {
        float p[NEXP], mx = -1e30f;
        #pragma unroll
        for (int e = 0; e < NEXP; e++) mx = fmaxf(mx, slog[e]);
        float sum = 0.f;
        #pragma unroll
        for (int e = 0; e < NEXP; e++) { p[e] = expf(slog[e] - mx); sum += p[e]; }
        const float inv = 1.f / sum;
        float score[NEXP];
        #pragma unroll
        for (int e = 0; e < NEXP; e++) { p[e] *= inv; score[e] = p[e] + gb[e]; }

        int sel[TOPK]; float wsum = 0.f;
        #pragma unroll
        for (int k = 0; k < TOPK; k++) {
            int best = 0; float bv = -1e30f;
            #pragma unroll
            for (int e = 0; e < NEXP; e++)
                if (score[e] > bv) { bv = score[e]; best = e; }
            sel[k] = best; score[best] = -1e31f; wsum += p[best];
        }
        const float invw = 1.f / wsum;
        #pragma unroll
        for (int k = 0; k < TOPK; k++) {
            g_topidx[t*TOPK + k] = sel[k];
            g_topw [t*TOPK + k] = p[sel[k]] * invw;
            atomicAdd(&g_counts[sel[k]], 1);
        }
    }
}

__global__ void zero_meta()
{
    int i = threadIdx.x;
    if (i < NEXP) { g_counts[i] = 0; g_fill[i] = 0; }
}

__global__ void sched_kernel()
{
    const int tid = threadIdx.x;
    if (tid == 0) {
        int base = 0;
        for (int e = 0; e < NEXP; e++) {
            g_offsets[e] = base;
            int nt = (g_counts[e] + BM - 1) / BM;
            int t0 = base / BM;
            for (int j = 0; j < nt; j++) g_tile_expert[t0 + j] = e;
            base += nt * BM;
        }
        for (int tl = base / BM; tl < MAXTILES; tl++) g_tile_expert[tl] = -1;
    }
    for (int i = tid; i < MAXROWS; i += blockDim.x) g_rowtok[i] = -1;
}

__global__ void scatter_kernel()
{
    const int p = blockIdx.x * blockDim.x + threadIdx.x;
    if (p >= T_TOK*TOPK) return;
    const int e = g_topidx[p];
    const int r = atomicAdd(&g_fill[e], 1);
    const int pos = g_offsets[e] + r;
    g_rowtok[pos] = p >> 2;
    g_posmap[p]   = pos;
}

// ======================= conversion kernels =======================
__device__ __forceinline__ void split_fp16(float v, __half& hi, __half& lo) {
    hi = __float2half(v);
    lo = __float2half(v - __half2float(hi));
}

// fp32 -> fp16 hi/lo (vector of 4)
__global__ void convert_x_kernel(const float* __restrict__ src,
                                 __half* __restrict__ dh,
                                 __half* __restrict__ dl, long long n4)
{
    long long p = (long long)blockIdx.x * blockDim.x + threadIdx.x;
    if (p >= n4) return;
    float4 v = ld4(src + p*4);
    union { __half b[4]; unsigned long long u; } H, L;
    split_fp16(v.x, H.b[0], L.b[0]);
    split_fp16(v.y, H.b[1], L.b[1]);
    split_fp16(v.z, H.b[2], L.b[2]);
    split_fp16(v.w, H.b[3], L.b[3]);
    *reinterpret_cast<unsigned long long*>(dh + p*4) = H.u;
    *reinterpret_cast<unsigned long long*>(dl + p*4) = L.u;
}

__global__ void gather_rows(const __half* __restrict__ xh,
                            const __half* __restrict__ xl,
                            __half* __restrict__ agh,
                            __half* __restrict__ agl)
{
    const int row = blockIdx.x;
    const int tid = threadIdx.x;   // 256 threads; DIM*2B = 4KB = 256x16B
    const int tok = g_rowtok[row];
    uint4* dh = reinterpret_cast<uint4*>(agh + (long long)row*DIM);
    uint4* dl = reinterpret_cast<uint4*>(agl + (long long)row*DIM);
    if (tok >= 0) {
        const uint4* sh = reinterpret_cast<const uint4*>(xh + (long long)tok*DIM);
        const uint4* sl = reinterpret_cast<const uint4*>(xl + (long long)tok*DIM);
        dh[tid] = sh[tid];
        dl[tid] = sl[tid];
    } else {
        uint4 z = make_uint4(0,0,0,0);
        dh[tid] = z; dl[tid] = z;
    }
}

// fp32 src [E][R][C] -> single fp16 dst [E][C][R]  (transpose + convert)
// glu_half H != 0: remap dest row so each 128-row group = 64 gate rows + 64 up rows.
__global__ void transpose_convert(const float* __restrict__ src,
                                  __half* __restrict__ dst,
                                  int R, int C, int glu_half)
{
    __shared__ float t[32][33];
    const int e  = blockIdx.z;
    const int c0 = blockIdx.x * 32;
    const int r0 = blockIdx.y * 32;
    const int tx = threadIdx.x, ty = threadIdx.y;   // (32, 8)
    const float* s = src + (long long)e*R*C;
    #pragma unroll
    for (int j = 0; j < 32; j += 8)
        t[ty+j][tx] = s[(long long)(r0+ty+j)*C + c0+tx];
    __syncthreads();
    __half* o = dst + (long long)e*C*R;
    #pragma unroll
    for (int j = 0; j < 32; j += 8) {
        float v = t[tx][ty+j];
        int c = c0 + ty + j;
        long long dr;
        if (glu_half == 0) dr = c;
        else if (c < glu_half) dr = (long long)(c >> 6)*128 + (c & 63);
        else { int cc = c - glu_half; dr = (long long)(cc >> 6)*128 + 64 + (cc & 63); }
        o[dr*R + r0+tx] = __float2half(v);
    }
}

// ======================= mma.sync GEMM core =======================
// C tile 128x128. A [M,K] fp16 hi/lo, B [N,K] single fp16 (both K-contig).
// 2-mma scheme: C = Ah*B + Al*B  (A repr exact to ~2^-21; only W rounding error)
// 256 threads = 8 warps (2 M x 4 N); warp tile 64x32; mma m16n8k16; k-step 16.
// Stage = A 8KB (64B rows: hi chunks 0-1, lo 2-3) + B 4KB (32B rows) = 12KB.
// 4 stages = 48KB static.  A swizzle c^((r>>1)&3); B swizzle c^((r>>2)&1).

#define SWZ64(r, c) ((uint32_t)(r)*64u + ((uint32_t)(((c) ^ (((r)>>1)&3))) << 4))
#define SWZB(r, c)  ((uint32_t)(r)*32u + ((uint32_t)(((c) ^ (((r)>>2)&1))) << 4))
#define B_OFF 8192
#define STGB  12288

__device__ __forceinline__ void cp16(uint32_t d, const void* s) {
    asm volatile("cp.async.cg.shared.global [%0], [%1], 16;\n" :: "r"(d), "l"(s));
}
__device__ __forceinline__ void ldm4(uint32_t* r, uint32_t a) {
    asm volatile("ldmatrix.sync.aligned.m8n8.x4.shared.b16 {%0,%1,%2,%3}, [%4];\n"
        : "=r"(r[0]), "=r"(r[1]), "=r"(r[2]), "=r"(r[3]) : "r"(a));
}
__device__ __forceinline__ void mma16816(float* c, const uint32_t* a, uint32_t b0, uint32_t b1) {
    asm volatile("mma.sync.aligned.m16n8k16.row.col.f32.f16.f16.f32 "
        "{%0,%1,%2,%3}, {%4,%5,%6,%7}, {%8,%9}, {%0,%1,%2,%3};\n"
        : "+f"(c[0]), "+f"(c[1]), "+f"(c[2]), "+f"(c[3])
        : "r"(a[0]), "r"(a[1]), "r"(a[2]), "r"(a[3]), "r"(b0), "r"(b1));
}

__device__ __forceinline__ void load_stage(uint32_t st,
    const __half* __restrict__ Ah, const __half* __restrict__ Al,
    const __half* __restrict__ B,
    int am0, int bn0, int ldk, int k0, int tid)
{
    const int row = tid >> 1;          // 0..127
    const int cb  = tid & 1;
    const size_t ga = (size_t)(am0+row)*ldk + k0 + cb*8;
    cp16(st +         SWZ64(row, cb),     Ah + ga);
    cp16(st +         SWZ64(row, 2 + cb), Al + ga);
    const size_t gb = (size_t)(bn0+row)*ldk + k0 + cb*8;
    cp16(st + B_OFF + SWZB(row, cb),      B + gb);
}

__device__ __forceinline__ void gemm_mainloop(uint32_t sb,
    const __half* __restrict__ Ah, const __half* __restrict__ Al,
    const __half* __restrict__ B,
    int m0, int brow0, int K, int tid, int lane, int wm, int wn,
    float acc[4][4][4])
{
    const int nk = K / 16;   // >= 64 always

    load_stage(sb,          Ah, Al, B, m0, brow0, K, 0,  tid);
    asm volatile("cp.async.commit_group;\n");
    load_stage(sb + STGB,   Ah, Al, B, m0, brow0, K, 16, tid);
    asm volatile("cp.async.commit_group;\n");
    load_stage(sb + 2*STGB, Ah, Al, B, m0, brow0, K, 32, tid);
    asm volatile("cp.async.commit_group;\n");

    for (int kt = 0; kt < nk; kt++) {
        asm volatile("cp.async.wait_group 2;\n");
        __syncthreads();

        if (kt + 3 < nk)
            load_stage(sb + ((kt+3)&3)*STGB, Ah, Al, B, m0, brow0, K, (kt+3)*16, tid);
        asm volatile("cp.async.commit_group;\n");

        const uint32_t Ab = sb + (kt & 3)*STGB;

        // B fragments: 2 x n16k16 per warp (single fp16)
        uint32_t fb[2][4];
        #pragma unroll
        for (int np = 0; np < 2; np++) {
            const int rb = wn*32 + np*16 + (lane & 7) + ((lane >> 4) << 3);
            const int cb = (lane >> 3) & 1;
            ldm4(fb[np], Ab + B_OFF + SWZB(rb, cb));
        }

        #pragma unroll
        for (int mt = 0; mt < 4; mt++) {
            uint32_t fah[4], fal[4];
            const int ra = wm*64 + mt*16 + (lane & 15);
            const int ca = lane >> 4;
            ldm4(fah, Ab + SWZ64(ra, ca));
            ldm4(fal, Ab + SWZ64(ra, 2 + ca));
            #pragma unroll
            for (int nt = 0; nt < 4; nt++) {
                const int np = nt >> 1, hx = (nt & 1)*2;
                mma16816(acc[mt][nt], fah, fb[np][hx], fb[np][hx+1]);
                mma16816(acc[mt][nt], fal, fb[np][hx], fb[np][hx+1]);
            }
        }
    }
    asm volatile("cp.async.wait_group 0;\n");
}

// ---------- merged gate_up GEMM with fused SwiGLU epilogue ----------
// grid.x = 1792: [0,1280) routed (16 x-tiles, 80 y), [1280,1792) shared (32 x, 16 y)
// B rows interleaved: tile x rows = 64 gate cols + 64 up cols (same 64 h-columns).
__global__ void __launch_bounds__(256, 2) gemm_gu_fused(
    const __half* __restrict__ Ah_r, const __half* __restrict__ Al_r,
    const __half* __restrict__ B_r,
    __half* __restrict__ Ch_r, __half* __restrict__ Cl_r,
    const __half* __restrict__ Ah_s, const __half* __restrict__ Al_s,
    const __half* __restrict__ B_s,
    __half* __restrict__ Ch_s, __half* __restrict__ Cl_s,
    const int* __restrict__ tile_expert)
{
    __shared__ char smem[4*STGB];      // 48KB; reused as fp32 gate[128][65] in epilogue
    const uint32_t sb = smem_to_u32(smem);

    const __half *Ah, *Al, *B;
    __half *Ch, *Cl;
    int m0, brow0, ldh, hcol0;
    int bid = blockIdx.x;
    if (bid < 1280) {
        const int bx = bid & 15, by = bid >> 4;
        const int e = tile_expert[by];
        if (e < 0) return;
        m0 = by*128; hcol0 = bx*64;
        brow0 = e*(2*IDIM) + bx*128;
        Ah = Ah_r; Al = Al_r; B = B_r; Ch = Ch_r; Cl = Cl_r;
        ldh = IDIM;
    } else {
        bid -= 1280;
        const int bx = bid & 31, by = bid >> 5;
        m0 = by*128; hcol0 = bx*64;
        brow0 = bx*128;
        Ah = Ah_s; Al = Al_s; B = B_s; Ch = Ch_s; Cl = Cl_s;
        ldh = SIDIM;
    }

    const int tid = threadIdx.x, lane = tid & 31, wid = tid >> 5;
    const int wm = wid & 1, wn = wid >> 1;

    float acc[4][4][4];
    #pragma unroll
    for (int a = 0; a < 4; a++)
        #pragma unroll
        for (int b = 0; b < 4; b++)
            #pragma unroll
            for (int c = 0; c < 4; c++) acc[a][b][c] = 0.f;

    gemm_mainloop(sb, Ah, Al, B, m0, brow0, DIM, tid, lane, wm, wn, acc);

    // ---- fused SwiGLU epilogue ----
    float* gs = reinterpret_cast<float*>(smem);   // [128][65] fp32 = 33280 B
    __syncthreads();                               // smem repurpose barrier

    if (wn < 2) {
        // gate warps: tile cols 0..63 -> stage to smem
        #pragma unroll
        for (int mt = 0; mt < 4; mt++)
            #pragma unroll
            for (int nt = 0; nt < 4; nt++) {
                const int r = wm*64 + mt*16 + (lane >> 2);
                const int c = wn*32 + nt*8 + (lane & 3)*2;
                gs[r*65 + c]       = acc[mt][nt][0];
                gs[r*65 + c + 1]   = acc[mt][nt][1];
                gs[(r+8)*65 + c]   = acc[mt][nt][2];
                gs[(r+8)*65 + c+1] = acc[mt][nt][3];
            }
    }
    __syncthreads();

    if (wn >= 2) {
        // up warps: tile cols 64..127 -> h cols 0..63
        #pragma unroll
        for (int mt = 0; mt < 4; mt++)
            #pragma unroll
            for (int nt = 0; nt < 4; nt++) {
                const int r = wm*64 + mt*16 + (lane >> 2);
                const int j = (wn-2)*32 + nt*8 + (lane & 3)*2;
                #pragma unroll
                for (int half = 0; half < 2; half++) {
                    const int rr = r + half*8;
                    const float g0 = gs[rr*65 + j];
                    const float g1 = gs[rr*65 + j + 1];
                    const float u0 = acc[mt][nt][half*2];
                    const float u1 = acc[mt][nt][half*2 + 1];
                    const float h0 = (g0 / (1.f + expf(-g0))) * u0;
                    const float h1 = (g1 / (1.f + expf(-g1))) * u1;
                    union { __half b[2]; uint32_t u; } H, L;
                    split_fp16(h0, H.b[0], L.b[0]);
                    split_fp16(h1, H.b[1], L.b[1]);
                    const long long off = (long long)(m0 + rr)*ldh + hcol0 + j;
                    *reinterpret_cast<uint32_t*>(Ch + off) = H.u;
                    *reinterpret_cast<uint32_t*>(Cl + off) = L.u;
                }
            }
    }
}

// ---------- merged down GEMM (fp32 epilogue) ----------
// grid.x = 1536: [0,1280) routed (16 x, 80 y, K=IDIM), [1280,1536) shared (16 x, 16 y, K=SIDIM)
__global__ void __launch_bounds__(256, 2) gemm_down_merged(
    const __half* __restrict__ Ah_r, const __half* __restrict__ Al_r,
    const __half* __restrict__ B_r, float* __restrict__ C_r,
    const __half* __restrict__ Ah_s, const __half* __restrict__ Al_s,
    const __half* __restrict__ B_s, float* __restrict__ C_s,
    const int* __restrict__ tile_expert)
{
    __shared__ char smem[4*STGB];
    const uint32_t sb = smem_to_u32(smem);

    const __half *Ah, *Al, *B;
    float* C;
    int m0, n0, brow0, K;
    int bid = blockIdx.x;
    if (bid < 1280) {
        const int bx = bid & 15, by = bid >> 4;
        const int e = tile_expert[by];
        if (e < 0) return;
        m0 = by*128; n0 = bx*128;
        brow0 = e*DIM + n0;
        Ah = Ah_r; Al = Al_r; B = B_r; C = C_r;
        K = IDIM;
    } else {
        bid -= 1280;
        const int bx = bid & 15, by = bid >> 4;
        m0 = by*128; n0 = bx*128;
        brow0 = n0;
        Ah = Ah_s; Al = Al_s; B = B_s; C = C_s;
        K = SIDIM;
    }

    const int tid = threadIdx.x, lane = tid & 31, wid = tid >> 5;
    const int wm = wid & 1, wn = wid >> 1;

    float acc[4][4][4];
    #pragma unroll
    for (int a = 0; a < 4; a++)
        #pragma unroll
        for (int b = 0; b < 4; b++)
            #pragma unroll
            for (int c = 0; c < 4; c++) acc[a][b][c] = 0.f;

    gemm_mainloop(sb, Ah, Al, B, m0, brow0, K, tid, lane, wm, wn, acc);

    const int rbase = m0 + wm*64 + (lane >> 2);
    const int cbase = n0 + wn*32 + (lane & 3)*2;
    #pragma unroll
    for (int mt = 0; mt < 4; mt++)
        #pragma unroll
        for (int nt = 0; nt < 4; nt++) {
            const long long r0 = rbase + mt*16;
            const int c0 = cbase + nt*8;
            *reinterpret_cast<float2*>(C + r0*DIM + c0) =
                make_float2(acc[mt][nt][0], acc[mt][nt][1]);
            *reinterpret_cast<float2*>(C + (r0+8)*DIM + c0) =
                make_float2(acc[mt][nt][2], acc[mt][nt][3]);
        }
}

// ======================= combine =======================
__global__ void combine_kernel(float* __restrict__ out)
{
    const int t = blockIdx.x;
    __shared__ int   spos[TOPK];
    __shared__ float sw[TOPK];
    if (threadIdx.x < TOPK) {
        spos[threadIdx.x] = g_posmap[t*TOPK + threadIdx.x];
        sw[threadIdx.x]   = g_topw [t*TOPK + threadIdx.x];
    }
    __syncthreads();
    for (int d = threadIdx.x*4; d < DIM; d += blockDim.x*4) {
        float4 a = ld4(out + (long long)t*DIM + d);
        #pragma unroll
        for (int k = 0; k < TOPK; k++) {
            const float4 ev = ld4(g_eout + (long long)spos[k]*DIM + d);
            const float wk = sw[k];
            a.x = fmaf(wk, ev.x, a.x); a.y = fmaf(wk, ev.y, a.y);
            a.z = fmaf(wk, ev.z, a.z); a.w = fmaf(wk, ev.w, a.w);
        }
        *reinterpret_cast<float4*>(out + (long long)t*DIM + d) = a;
    }
}

// ======================= host =======================
extern "C" void kernel_launch(void* const* d_in, const int* in_sizes, int n_in,
                              void* d_out, int out_size)
{
    const float* x    = (const float*)d_in[0];
    const float* gw   = (const float*)d_in[1];
    const float* gb   = (const float*)d_in[2];
    const float* wgu  = (const float*)d_in[3];
    const float* wd   = (const float*)d_in[4];
    const float* wsgu = (const float*)d_in[5];
    const float* wsd  = (const float*)d_in[6];
    float* out = (float*)d_out;

    void *xh, *xl, *agh, *agl, *wguT, *wdT, *wsguT, *wsdT,
         *hbh, *hbl, *hshh, *hshl, *eout, *tilee;
    cudaGetSymbolAddress(&xh, g_xh);       cudaGetSymbolAddress(&xl, g_xl);
    cudaGetSymbolAddress(&agh, g_agh);     cudaGetSymbolAddress(&agl, g_agl);
    cudaGetSymbolAddress(&wguT, g_wguT);   cudaGetSymbolAddress(&wdT, g_wdT);
    cudaGetSymbolAddress(&wsguT, g_wsguT); cudaGetSymbolAddress(&wsdT, g_wsdT);
    cudaGetSymbolAddress(&hbh, g_hbh);     cudaGetSymbolAddress(&hbl, g_hbl);
    cudaGetSymbolAddress(&hshh, g_hsh_h);  cudaGetSymbolAddress(&hshl, g_hsh_l);
    cudaGetSymbolAddress(&eout, g_eout);
    cudaGetSymbolAddress(&tilee, g_tile_expert);

    // --- routing ---
    zero_meta<<<1, 32>>>();
    router_kernel<<<T_TOK, 512>>>(x, gw, gb);
    sched_kernel<<<1, 256>>>();
    scatter_kernel<<<(T_TOK*TOPK + 255)/256, 256>>>();

    // --- conversions ---
    convert_x_kernel<<<(T_TOK*DIM/4 + 255)/256, 256>>>(
        x, (__half*)xh, (__half*)xl, (long long)T_TOK*DIM/4);
    gather_rows<<<MAXROWS, 256>>>((const __half*)xh, (const __half*)xl,
                                  (__half*)agh, (__half*)agl);
    transpose_convert<<<dim3(2*IDIM/32, DIM/32, NEXP), dim3(32,8)>>>(
        wgu, (__half*)wguT, DIM, 2*IDIM, IDIM);
    transpose_convert<<<dim3(DIM/32, IDIM/32, NEXP), dim3(32,8)>>>(
        wd, (__half*)wdT, IDIM, DIM, 0);
    transpose_convert<<<dim3(2*SIDIM/32, DIM/32, 1), dim3(32,8)>>>(
        wsgu, (__half*)wsguT, DIM, 2*SIDIM, SIDIM);
    transpose_convert<<<dim3(DIM/32, SIDIM/32, 1), dim3(32,8)>>>(
        wsd, (__half*)wsdT, SIDIM, DIM, 0);

    // --- merged gate_up GEMM + fused SwiGLU (routed 1280 + shared 512 CTAs) ---
    gemm_gu_fused<<<1792, 256>>>(
        (const __half*)agh, (const __half*)agl, (const __half*)wguT,
        (__half*)hbh, (__half*)hbl,
        (const __half*)xh, (const __half*)xl, (const __half*)wsguT,
        (__half*)hshh, (__half*)hshl,
        (const int*)tilee);

    // --- merged down GEMM (routed 1280 + shared 256 CTAs) ---
    gemm_down_merged<<<1536, 256>>>(
        (const __half*)hbh, (const __half*)hbl, (const __half*)wdT, (float*)eout,
        (const __half*)hshh, (const __half*)hshl, (const __half*)wsdT, out,
        (const int*)tilee);

    // --- combine ---
    combine_kernel<<<T_TOK, 256>>>(out);
}

// round 13
// speedup vs baseline: 1.9869x; 1.4155x over previous
#include <cuda_runtime.h>
#include <cuda.h>
#include <cuda_fp16.h>
#include <math.h>
#include <stdint.h>

// Problem dims (fixed by setup_inputs)
#define T_TOK 2048
#define DIM   2048
#define NEXP  16
#define IDIM  1024
#define SIDIM 2048
#define TOPK  4

#define BM 128
#define MAXROWS (T_TOK*TOPK + NEXP*BM)   // 10240
#define MAXTILES (MAXROWS/BM)            // 80

// ======================= scratch (device globals) =======================
__device__ __half g_x16[(size_t)T_TOK*DIM];         // x fp16
__device__ __half g_ag[(size_t)MAXROWS*DIM];        // gathered rows fp16
__device__ __half g_wguT[(size_t)NEXP*2*IDIM*DIM];  // interleaved gate/up rows, fp16
__device__ __half g_wdT[(size_t)NEXP*DIM*IDIM];
__device__ __half g_wsguT[(size_t)2*SIDIM*DIM];     // interleaved
__device__ __half g_wsdT[(size_t)DIM*SIDIM];
__device__ __half g_hb[(size_t)MAXROWS*IDIM];       // routed hidden fp16
__device__ __half g_hsh[(size_t)T_TOK*SIDIM];       // shared hidden fp16
__device__ float g_eout[(size_t)MAXROWS*DIM];

__device__ int   g_topidx[T_TOK*TOPK];
__device__ float g_topw[T_TOK*TOPK];
__device__ int   g_counts[NEXP];
__device__ int   g_fill[NEXP];
__device__ int   g_offsets[NEXP];
__device__ int   g_tile_expert[MAXTILES];
__device__ int   g_rowtok[MAXROWS];
__device__ int   g_posmap[T_TOK*TOPK];

__device__ __forceinline__ float4 ld4(const float* p) {
    return *reinterpret_cast<const float4*>(p);
}

__device__ __forceinline__ uint32_t smem_to_u32(const void* smem_ptr) {
    uint32_t addr;
    asm("{ .reg .u64 tmp; cvta.to.shared.u64 tmp, %1; cvt.u32.u64 %0, tmp; }"
        : "=r"(addr) : "l"(smem_ptr));
    return addr;
}

// ======================= router / scheduling =======================
__global__ void router_kernel(const float* __restrict__ x,
                              const float* __restrict__ gw,
                              const float* __restrict__ gb)
{
    __shared__ float sx[DIM];
    __shared__ float slog[NEXP];
    const int t   = blockIdx.x;
    const int tid = threadIdx.x;           // 512 threads

    *reinterpret_cast<float4*>(&sx[tid*4]) = ld4(x + (long long)t*DIM + tid*4);
    __syncthreads();

    const int w = tid >> 5, lane = tid & 31;
    const float* gwr = gw + w*DIM;
    float s = 0.f;
    for (int i = lane*4; i < DIM; i += 32*4) {
        float4 xv = *reinterpret_cast<float4*>(&sx[i]);
        float4 gv = ld4(gwr + i);
        s += xv.x*gv.x + xv.y*gv.y + xv.z*gv.z + xv.w*gv.w;
    }
    #pragma unroll
    for (int o = 16; o; o >>= 1) s += __shfl_down_sync(0xffffffffu, s, o);
    if (lane == 0) slog[w] = s;
    __syncthreads();

    if (tid == 0) {
        float p[NEXP], mx = -1e30f;
        #pragma unroll
        for (int e = 0; e < NEXP; e++) mx = fmaxf(mx, slog[e]);
        float sum = 0.f;
        #pragma unroll
        for (int e = 0; e < NEXP; e++) { p[e] = expf(slog[e] - mx); sum += p[e]; }
        const float inv = 1.f / sum;
        float score[NEXP];
        #pragma unroll
        for (int e = 0; e < NEXP; e++) { p[e] *= inv; score[e] = p[e] + gb[e]; }

        int sel[TOPK]; float wsum = 0.f;
        #pragma unroll
        for (int k = 0; k < TOPK; k++) {
            int best = 0; float bv = -1e30f;
            #pragma unroll
            for (int e = 0; e < NEXP; e++)
                if (score[e] > bv) { bv = score[e]; best = e; }
            sel[k] = best; score[best] = -1e31f; wsum += p[best];
        }
        const float invw = 1.f / wsum;
        #pragma unroll
        for (int k = 0; k < TOPK; k++) {
            g_topidx[t*TOPK + k] = sel[k];
            g_topw [t*TOPK + k] = p[sel[k]] * invw;
            atomicAdd(&g_counts[sel[k]], 1);
        }
    }
}

__global__ void zero_meta()
{
    int i = threadIdx.x;
    if (i < NEXP) { g_counts[i] = 0; g_fill[i] = 0; }
}

__global__ void sched_kernel()
{
    const int tid = threadIdx.x;
    if (tid == 0) {
        int base = 0;
        for (int e = 0; e < NEXP; e++) {
            g_offsets[e] = base;
            int nt = (g_counts[e] + BM - 1) / BM;
            int t0 = base / BM;
            for (int j = 0; j < nt; j++) g_tile_expert[t0 + j] = e;
            base += nt * BM;
        }
        for (int tl = base / BM; tl < MAXTILES; tl++) g_tile_expert[tl] = -1;
    }
    for (int i = tid; i < MAXROWS; i += blockDim.x) g_rowtok[i] = -1;
}

__global__ void scatter_kernel()
{
    const int p = blockIdx.x * blockDim.x + threadIdx.x;
    if (p >= T_TOK*TOPK) return;
    const int e = g_topidx[p];
    const int r = atomicAdd(&g_fill[e], 1);
    const int pos = g_offsets[e] + r;
    g_rowtok[pos] = p >> 2;
    g_posmap[p]   = pos;
}

// ======================= conversion kernels =======================
// fp32 -> fp16 (vector of 4)
__global__ void convert_x_kernel(const float* __restrict__ src,
                                 __half* __restrict__ dst, long long n4)
{
    long long p = (long long)blockIdx.x * blockDim.x + threadIdx.x;
    if (p >= n4) return;
    float4 v = ld4(src + p*4);
    union { __half b[4]; unsigned long long u; } H;
    H.b[0] = __float2half(v.x); H.b[1] = __float2half(v.y);
    H.b[2] = __float2half(v.z); H.b[3] = __float2half(v.w);
    *reinterpret_cast<unsigned long long*>(dst + p*4) = H.u;
}

__global__ void gather_rows(const __half* __restrict__ x16,
                            __half* __restrict__ ag)
{
    const int row = blockIdx.x;
    const int tid = threadIdx.x;   // 256 threads; DIM*2B = 4KB = 256x16B
    const int tok = g_rowtok[row];
    uint4* d = reinterpret_cast<uint4*>(ag + (long long)row*DIM);
    if (tok >= 0) {
        const uint4* s = reinterpret_cast<const uint4*>(x16 + (long long)tok*DIM);
        d[tid] = s[tid];
    } else {
        d[tid] = make_uint4(0,0,0,0);
    }
}

// fp32 src [E][R][C] -> fp16 dst [E][C][R]  (transpose + convert)
// glu_half H != 0: remap dest row so each 128-row group = 64 gate rows + 64 up rows.
__global__ void transpose_convert(const float* __restrict__ src,
                                  __half* __restrict__ dst,
                                  int R, int C, int glu_half)
{
    __shared__ float t[32][33];
    const int e  = blockIdx.z;
    const int c0 = blockIdx.x * 32;
    const int r0 = blockIdx.y * 32;
    const int tx = threadIdx.x, ty = threadIdx.y;   // (32, 8)
    const float* s = src + (long long)e*R*C;
    #pragma unroll
    for (int j = 0; j < 32; j += 8)
        t[ty+j][tx] = s[(long long)(r0+ty+j)*C + c0+tx];
    __syncthreads();
    __half* o = dst + (long long)e*C*R;
    #pragma unroll
    for (int j = 0; j < 32; j += 8) {
        float v = t[tx][ty+j];
        int c = c0 + ty + j;
        long long dr;
        if (glu_half == 0) dr = c;
        else if (c < glu_half) dr = (long long)(c >> 6)*128 + (c & 63);
        else { int cc = c - glu_half; dr = (long long)(cc >> 6)*128 + 64 + (cc & 63); }
        o[dr*R + r0+tx] = __float2half(v);
    }
}

// ======================= mma.sync GEMM core (pure fp16) =======================
// C tile 128x128. A [M,K] fp16, B [N,K] fp16 (both K-contig). fp32 accum.
// 256 threads = 8 warps (2 M x 4 N); warp tile 64x32; mma m16n8k16; k-step 16.
// Stage = A 4KB + B 4KB = 8KB (32B rows, swizzle c^((r>>2)&1)); 4 stages = 32KB.

#define SWZB(r, c)  ((uint32_t)(r)*32u + ((uint32_t)(((c) ^ (((r)>>2)&1))) << 4))
#define B_OFF4 4096
#define STG8   8192

__device__ __forceinline__ void cp16(uint32_t d, const void* s) {
    asm volatile("cp.async.cg.shared.global [%0], [%1], 16;\n" :: "r"(d), "l"(s));
}
__device__ __forceinline__ void ldm4(uint32_t* r, uint32_t a) {
    asm volatile("ldmatrix.sync.aligned.m8n8.x4.shared.b16 {%0,%1,%2,%3}, [%4];\n"
        : "=r"(r[0]), "=r"(r[1]), "=r"(r[2]), "=r"(r[3]) : "r"(a));
}
__device__ __forceinline__ void mma16816(float* c, const uint32_t* a, uint32_t b0, uint32_t b1) {
    asm volatile("mma.sync.aligned.m16n8k16.row.col.f32.f16.f16.f32 "
        "{%0,%1,%2,%3}, {%4,%5,%6,%7}, {%8,%9}, {%0,%1,%2,%3};\n"
        : "+f"(c[0]), "+f"(c[1]), "+f"(c[2]), "+f"(c[3])
        : "r"(a[0]), "r"(a[1]), "r"(a[2]), "r"(a[3]), "r"(b0), "r"(b1));
}

__device__ __forceinline__ void load_stage(uint32_t st,
    const __half* __restrict__ A, const __half* __restrict__ B,
    int am0, int bn0, int ldk, int k0, int tid)
{
    const int row = tid >> 1;          // 0..127
    const int cb  = tid & 1;
    cp16(st +          SWZB(row, cb), A + (size_t)(am0+row)*ldk + k0 + cb*8);
    cp16(st + B_OFF4 + SWZB(row, cb), B + (size_t)(bn0+row)*ldk + k0 + cb*8);
}

__device__ __forceinline__ void gemm_mainloop(uint32_t sb,
    const __half* __restrict__ A, const __half* __restrict__ B,
    int m0, int brow0, int K, int tid, int lane, int wm, int wn,
    float acc[4][4][4])
{
    const int nk = K / 16;   // >= 64 always

    load_stage(sb,          A, B, m0, brow0, K, 0,  tid);
    asm volatile("cp.async.commit_group;\n");
    load_stage(sb + STG8,   A, B, m0, brow0, K, 16, tid);
    asm volatile("cp.async.commit_group;\n");
    load_stage(sb + 2*STG8, A, B, m0, brow0, K, 32, tid);
    asm volatile("cp.async.commit_group;\n");

    for (int kt = 0; kt < nk; kt++) {
        asm volatile("cp.async.wait_group 2;\n");
        __syncthreads();

        if (kt + 3 < nk)
            load_stage(sb + ((kt+3)&3)*STG8, A, B, m0, brow0, K, (kt+3)*16, tid);
        asm volatile("cp.async.commit_group;\n");

        const uint32_t Ab = sb + (kt & 3)*STG8;

        uint32_t fb[2][4];
        #pragma unroll
        for (int np = 0; np < 2; np++) {
            const int rb = wn*32 + np*16 + (lane & 7) + ((lane >> 4) << 3);
            const int cb = (lane >> 3) & 1;
            ldm4(fb[np], Ab + B_OFF4 + SWZB(rb, cb));
        }

        #pragma unroll
        for (int mt = 0; mt < 4; mt++) {
            uint32_t fa[4];
            const int ra = wm*64 + mt*16 + (lane & 15);
            const int ca = lane >> 4;
            ldm4(fa, Ab + SWZB(ra, ca));
            #pragma unroll
            for (int nt = 0; nt < 4; nt++) {
                const int np = nt >> 1, hx = (nt & 1)*2;
                mma16816(acc[mt][nt], fa, fb[np][hx], fb[np][hx+1]);
            }
        }
    }
    asm volatile("cp.async.wait_group 0;\n");
}

// ---------- merged gate_up GEMM with fused SwiGLU epilogue ----------
// grid.x = 1792: [0,1280) routed (16 x-tiles, 80 y), [1280,1792) shared (32 x, 16 y)
// B rows interleaved: tile x rows = 64 gate cols + 64 up cols (same 64 h-columns).
#define GU_SMEM 34816   // max(4 stages * 8KB, fp32 gate[128][65] = 33280)

__global__ void __launch_bounds__(256, 2) gemm_gu_fused(
    const __half* __restrict__ A_r, const __half* __restrict__ B_r,
    __half* __restrict__ C_r,
    const __half* __restrict__ A_s, const __half* __restrict__ B_s,
    __half* __restrict__ C_s,
    const int* __restrict__ tile_expert)
{
    __shared__ char smem[GU_SMEM];
    const uint32_t sb = smem_to_u32(smem);

    const __half *A, *B;
    __half *C;
    int m0, brow0, ldh, hcol0;
    int bid = blockIdx.x;
    if (bid < 1280) {
        const int bx = bid & 15, by = bid >> 4;
        const int e = tile_expert[by];
        if (e < 0) return;
        m0 = by*128; hcol0 = bx*64;
        brow0 = e*(2*IDIM) + bx*128;
        A = A_r; B = B_r; C = C_r;
        ldh = IDIM;
    } else {
        bid -= 1280;
        const int bx = bid & 31, by = bid >> 5;
        m0 = by*128; hcol0 = bx*64;
        brow0 = bx*128;
        A = A_s; B = B_s; C = C_s;
        ldh = SIDIM;
    }

    const int tid = threadIdx.x, lane = tid & 31, wid = tid >> 5;
    const int wm = wid & 1, wn = wid >> 1;

    float acc[4][4][4];
    #pragma unroll
    for (int a = 0; a < 4; a++)
        #pragma unroll
        for (int b = 0; b < 4; b++)
            #pragma unroll
            for (int c = 0; c < 4; c++) acc[a][b][c] = 0.f;

    gemm_mainloop(sb, A, B, m0, brow0, DIM, tid, lane, wm, wn, acc);

    // ---- fused SwiGLU epilogue ----
    float* gs = reinterpret_cast<float*>(smem);   // [128][65] fp32 = 33280 B
    __syncthreads();                               // smem repurpose barrier

    if (wn < 2) {
        // gate warps: tile cols 0..63 -> stage to smem
        #pragma unroll
        for (int mt = 0; mt < 4; mt++)
            #pragma unroll
            for (int nt = 0; nt < 4; nt++) {
                const int r = wm*64 + mt*16 + (lane >> 2);
                const int c = wn*32 + nt*8 + (lane & 3)*2;
                gs[r*65 + c]       = acc[mt][nt][0];
                gs[r*65 + c + 1]   = acc[mt][nt][1];
                gs[(r+8)*65 + c]   = acc[mt][nt][2];
                gs[(r+8)*65 + c+1] = acc[mt][nt][3];
            }
    }
    __syncthreads();

    if (wn >= 2) {
        // up warps: tile cols 64..127 -> h cols 0..63
        #pragma unroll
        for (int mt = 0; mt < 4; mt++)
            #pragma unroll
            for (int nt = 0; nt < 4; nt++) {
                const int r = wm*64 + mt*16 + (lane >> 2);
                const int j = (wn-2)*32 + nt*8 + (lane & 3)*2;
                #pragma unroll
                for (int half = 0; half < 2; half++) {
                    const int rr = r + half*8;
                    const float g0 = gs[rr*65 + j];
                    const float g1 = gs[rr*65 + j + 1];
                    const float u0 = acc[mt][nt][half*2];
                    const float u1 = acc[mt][nt][half*2 + 1];
                    const float h0 = (g0 / (1.f + expf(-g0))) * u0;
                    const float h1 = (g1 / (1.f + expf(-g1))) * u1;
                    union { __half b[2]; uint32_t u; } H;
                    H.b[0] = __float2half(h0);
                    H.b[1] = __float2half(h1);
                    const long long off = (long long)(m0 + rr)*ldh + hcol0 + j;
                    *reinterpret_cast<uint32_t*>(C + off) = H.u;
                }
            }
    }
}

// ---------- merged down GEMM (fp32 epilogue) ----------
// grid.x = 1536: [0,1280) routed (16 x, 80 y, K=IDIM), [1280,1536) shared (16 x, 16 y, K=SIDIM)
__global__ void __launch_bounds__(256, 2) gemm_down_merged(
    const __half* __restrict__ A_r, const __half* __restrict__ B_r,
    float* __restrict__ C_r,
    const __half* __restrict__ A_s, const __half* __restrict__ B_s,
    float* __restrict__ C_s,
    const int* __restrict__ tile_expert)
{
    __shared__ char smem[4*STG8];
    const uint32_t sb = smem_to_u32(smem);

    const __half *A, *B;
    float* C;
    int m0, n0, brow0, K;
    int bid = blockIdx.x;
    if (bid < 1280) {
        const int bx = bid & 15, by = bid >> 4;
        const int e = tile_expert[by];
        if (e < 0) return;
        m0 = by*128; n0 = bx*128;
        brow0 = e*DIM + n0;
        A = A_r; B = B_r; C = C_r;
        K = IDIM;
    } else {
        bid -= 1280;
        const int bx = bid & 15, by = bid >> 4;
        m0 = by*128; n0 = bx*128;
        brow0 = n0;
        A = A_s; B = B_s; C = C_s;
        K = SIDIM;
    }

    const int tid = threadIdx.x, lane = tid & 31, wid = tid >> 5;
    const int wm = wid & 1, wn = wid >> 1;

    float acc[4][4][4];
    #pragma unroll
    for (int a = 0; a < 4; a++)
        #pragma unroll
        for (int b = 0; b < 4; b++)
            #pragma unroll
            for (int c = 0; c < 4; c++) acc[a][b][c] = 0.f;

    gemm_mainloop(sb, A, B, m0, brow0, K, tid, lane, wm, wn, acc);

    const int rbase = m0 + wm*64 + (lane >> 2);
    const int cbase = n0 + wn*32 + (lane & 3)*2;
    #pragma unroll
    for (int mt = 0; mt < 4; mt++)
        #pragma unroll
        for (int nt = 0; nt < 4; nt++) {
            const long long r0 = rbase + mt*16;
            const int c0 = cbase + nt*8;
            *reinterpret_cast<float2*>(C + r0*DIM + c0) =
                make_float2(acc[mt][nt][0], acc[mt][nt][1]);
            *reinterpret_cast<float2*>(C + (r0+8)*DIM + c0) =
                make_float2(acc[mt][nt][2], acc[mt][nt][3]);
        }
}

// ======================= combine =======================
__global__ void combine_kernel(float* __restrict__ out)
{
    const int t = blockIdx.x;
    __shared__ int   spos[TOPK];
    __shared__ float sw[TOPK];
    if (threadIdx.x < TOPK) {
        spos[threadIdx.x] = g_posmap[t*TOPK + threadIdx.x];
        sw[threadIdx.x]   = g_topw [t*TOPK + threadIdx.x];
    }
    __syncthreads();
    for (int d = threadIdx.x*4; d < DIM; d += blockDim.x*4) {
        float4 a = ld4(out + (long long)t*DIM + d);
        #pragma unroll
        for (int k = 0; k < TOPK; k++) {
            const float4 ev = ld4(g_eout + (long long)spos[k]*DIM + d);
            const float wk = sw[k];
            a.x = fmaf(wk, ev.x, a.x); a.y = fmaf(wk, ev.y, a.y);
            a.z = fmaf(wk, ev.z, a.z); a.w = fmaf(wk, ev.w, a.w);
        }
        *reinterpret_cast<float4*>(out + (long long)t*DIM + d) = a;
    }
}

// ======================= host =======================
extern "C" void kernel_launch(void* const* d_in, const int* in_sizes, int n_in,
                              void* d_out, int out_size)
{
    const float* x    = (const float*)d_in[0];
    const float* gw   = (const float*)d_in[1];
    const float* gb   = (const float*)d_in[2];
    const float* wgu  = (const float*)d_in[3];
    const float* wd   = (const float*)d_in[4];
    const float* wsgu = (const float*)d_in[5];
    const float* wsd  = (const float*)d_in[6];
    float* out = (float*)d_out;

    void *x16, *ag, *wguT, *wdT, *wsguT, *wsdT,
         *hb, *hsh, *eout, *tilee;
    cudaGetSymbolAddress(&x16, g_x16);
    cudaGetSymbolAddress(&ag, g_ag);
    cudaGetSymbolAddress(&wguT, g_wguT);   cudaGetSymbolAddress(&wdT, g_wdT);
    cudaGetSymbolAddress(&wsguT, g_wsguT); cudaGetSymbolAddress(&wsdT, g_wsdT);
    cudaGetSymbolAddress(&hb, g_hb);       cudaGetSymbolAddress(&hsh, g_hsh);
    cudaGetSymbolAddress(&eout, g_eout);
    cudaGetSymbolAddress(&tilee, g_tile_expert);

    // --- routing ---
    zero_meta<<<1, 32>>>();
    router_kernel<<<T_TOK, 512>>>(x, gw, gb);
    sched_kernel<<<1, 256>>>();
    scatter_kernel<<<(T_TOK*TOPK + 255)/256, 256>>>();

    // --- conversions ---
    convert_x_kernel<<<(T_TOK*DIM/4 + 255)/256, 256>>>(
        x, (__half*)x16, (long long)T_TOK*DIM/4);
    gather_rows<<<MAXROWS, 256>>>((const __half*)x16, (__half*)ag);
    transpose_convert<<<dim3(2*IDIM/32, DIM/32, NEXP), dim3(32,8)>>>(
        wgu, (__half*)wguT, DIM, 2*IDIM, IDIM);
    transpose_convert<<<dim3(DIM/32, IDIM/32, NEXP), dim3(32,8)>>>(
        wd, (__half*)wdT, IDIM, DIM, 0);
    transpose_convert<<<dim3(2*SIDIM/32, DIM/32, 1), dim3(32,8)>>>(
        wsgu, (__half*)wsguT, DIM, 2*SIDIM, SIDIM);
    transpose_convert<<<dim3(DIM/32, SIDIM/32, 1), dim3(32,8)>>>(
        wsd, (__half*)wsdT, SIDIM, DIM, 0);

    // --- merged gate_up GEMM + fused SwiGLU (routed 1280 + shared 512 CTAs) ---
    gemm_gu_fused<<<1792, 256>>>(
        (const __half*)ag, (const __half*)wguT, (__half*)hb,
        (const __half*)x16, (const __half*)wsguT, (__half*)hsh,
        (const int*)tilee);

    // --- merged down GEMM (routed 1280 + shared 256 CTAs) ---
    gemm_down_merged<<<1536, 256>>>(
        (const __half*)hb, (const __half*)wdT, (float*)eout,
        (const __half*)hsh, (const __half*)wsdT, out,
        (const int*)tilee);

    // --- combine ---
    combine_kernel<<<T_TOK, 256>>>(out);
}

// round 14
// speedup vs baseline: 2.0041x; 1.0087x over previous
#include <cuda_runtime.h>
#include <cuda.h>
#include <cuda_fp16.h>
#include <math.h>
#include <stdint.h>

// Problem dims (fixed by setup_inputs)
#define T_TOK 2048
#define DIM   2048
#define NEXP  16
#define IDIM  1024
#define SIDIM 2048
#define TOPK  4

#define BM 128
#define MAXROWS (T_TOK*TOPK + NEXP*BM)   // 10240
#define MAXTILES (MAXROWS/BM)            // 80

// ======================= scratch (device globals) =======================
__device__ __half g_x16[(size_t)T_TOK*DIM];         // x fp16
__device__ __half g_zero[DIM];                      // zero row (static zero-init)
__device__ __half g_wguT[(size_t)NEXP*2*IDIM*DIM];  // interleaved gate/up rows, fp16
__device__ __half g_wdT[(size_t)NEXP*DIM*IDIM];
__device__ __half g_wsguT[(size_t)2*SIDIM*DIM];     // interleaved
__device__ __half g_wsdT[(size_t)DIM*SIDIM];
__device__ __half g_hb[(size_t)MAXROWS*IDIM];       // routed hidden fp16
__device__ __half g_hsh[(size_t)T_TOK*SIDIM];       // shared hidden fp16
__device__ float g_eout[(size_t)MAXROWS*DIM];

__device__ int   g_topidx[T_TOK*TOPK];
__device__ float g_topw[T_TOK*TOPK];
__device__ int   g_counts[NEXP];
__device__ int   g_fill[NEXP];
__device__ int   g_offsets[NEXP];
__device__ int   g_tile_expert[MAXTILES];
__device__ int   g_rowtok[MAXROWS];
__device__ int   g_posmap[T_TOK*TOPK];

__device__ __forceinline__ float4 ld4(const float* p) {
    return *reinterpret_cast<const float4*>(p);
}

__device__ __forceinline__ uint32_t smem_to_u32(const void* smem_ptr) {
    uint32_t addr;
    asm("{ .reg .u64 tmp; cvta.to.shared.u64 tmp, %1; cvt.u32.u64 %0, tmp; }"
        : "=r"(addr) : "l"(smem_ptr));
    return addr;
}

// ======================= router (+ fused x fp32->fp16) =======================
__global__ void router_kernel(const float* __restrict__ x,
                              const float* __restrict__ gw,
                              const float* __restrict__ gb,
                              __half* __restrict__ x16)
{
    __shared__ float sx[DIM];
    __shared__ float slog[NEXP];
    const int t   = blockIdx.x;
    const int tid = threadIdx.x;           // 512 threads

    float4 xv0 = ld4(x + (long long)t*DIM + tid*4);
    *reinterpret_cast<float4*>(&sx[tid*4]) = xv0;
    // fused conversion: write fp16 copy of this token row
    {
        union { __half b[4]; unsigned long long u; } H;
        H.b[0] = __float2half(xv0.x); H.b[1] = __float2half(xv0.y);
        H.b[2] = __float2half(xv0.z); H.b[3] = __float2half(xv0.w);
        *reinterpret_cast<unsigned long long*>(x16 + (long long)t*DIM + tid*4) = H.u;
    }
    __syncthreads();

    const int w = tid >> 5, lane = tid & 31;
    const float* gwr = gw + w*DIM;
    float s = 0.f;
    for (int i = lane*4; i < DIM; i += 32*4) {
        float4 xv = *reinterpret_cast<float4*>(&sx[i]);
        float4 gv = ld4(gwr + i);
        s += xv.x*gv.x + xv.y*gv.y + xv.z*gv.z + xv.w*gv.w;
    }
    #pragma unroll
    for (int o = 16; o; o >>= 1) s += __shfl_down_sync(0xffffffffu, s, o);
    if (lane == 0) slog[w] = s;
    __syncthreads();

    if (tid == 0) {
        float p[NEXP], mx = -1e30f;
        #pragma unroll
        for (int e = 0; e < NEXP; e++) mx = fmaxf(mx, slog[e]);
        float sum = 0.f;
        #pragma unroll
        for (int e = 0; e < NEXP; e++) { p[e] = expf(slog[e] - mx); sum += p[e]; }
        const float inv = 1.f / sum;
        float score[NEXP];
        #pragma unroll
        for (int e = 0; e < NEXP; e++) { p[e] *= inv; score[e] = p[e] + gb[e]; }

        int sel[TOPK]; float wsum = 0.f;
        #pragma unroll
        for (int k = 0; k < TOPK; k++) {
            int best = 0; float bv = -1e30f;
            #pragma unroll
            for (int e = 0; e < NEXP; e++)
                if (score[e] > bv) { bv = score[e]; best = e; }
            sel[k] = best; score[best] = -1e31f; wsum += p[best];
        }
        const float invw = 1.f / wsum;
        #pragma unroll
        for (int k = 0; k < TOPK; k++) {
            g_topidx[t*TOPK + k] = sel[k];
            g_topw [t*TOPK + k] = p[sel[k]] * invw;
            atomicAdd(&g_counts[sel[k]], 1);
        }
    }
}

__global__ void zero_meta()
{
    int i = threadIdx.x;
    if (i < NEXP) { g_counts[i] = 0; g_fill[i] = 0; }
}

__global__ void sched_kernel()
{
    const int tid = threadIdx.x;
    if (tid == 0) {
        int base = 0;
        for (int e = 0; e < NEXP; e++) {
            g_offsets[e] = base;
            int nt = (g_counts[e] + BM - 1) / BM;
            int t0 = base / BM;
            for (int j = 0; j < nt; j++) g_tile_expert[t0 + j] = e;
            base += nt * BM;
        }
        for (int tl = base / BM; tl < MAXTILES; tl++) g_tile_expert[tl] = -1;
    }
    for (int i = tid; i < MAXROWS; i += blockDim.x) g_rowtok[i] = -1;
}

__global__ void scatter_kernel()
{
    const int p = blockIdx.x * blockDim.x + threadIdx.x;
    if (p >= T_TOK*TOPK) return;
    const int e = g_topidx[p];
    const int r = atomicAdd(&g_fill[e], 1);
    const int pos = g_offsets[e] + r;
    g_rowtok[pos] = p >> 2;
    g_posmap[p]   = pos;
}

// ======================= weight conversion =======================
// fp32 src [E][R][C] -> fp16 dst [E][C][R]  (transpose + convert)
// glu_half H != 0: remap dest row so each 128-row group = 64 gate rows + 64 up rows.
__global__ void transpose_convert(const float* __restrict__ src,
                                  __half* __restrict__ dst,
                                  int R, int C, int glu_half)
{
    __shared__ float t[32][33];
    const int e  = blockIdx.z;
    const int c0 = blockIdx.x * 32;
    const int r0 = blockIdx.y * 32;
    const int tx = threadIdx.x, ty = threadIdx.y;   // (32, 8)
    const float* s = src + (long long)e*R*C;
    #pragma unroll
    for (int j = 0; j < 32; j += 8)
        t[ty+j][tx] = s[(long long)(r0+ty+j)*C + c0+tx];
    __syncthreads();
    __half* o = dst + (long long)e*C*R;
    #pragma unroll
    for (int j = 0; j < 32; j += 8) {
        float v = t[tx][ty+j];
        int c = c0 + ty + j;
        long long dr;
        if (glu_half == 0) dr = c;
        else if (c < glu_half) dr = (long long)(c >> 6)*128 + (c & 63);
        else { int cc = c - glu_half; dr = (long long)(cc >> 6)*128 + 64 + (cc & 63); }
        o[dr*R + r0+tx] = __float2half(v);
    }
}

// ======================= mma.sync GEMM core (fp16, k-step 32) =======================
// C tile 128x128. A via per-thread row pointer, B [N,K] fp16 K-contig. fp32 accum.
// 256 threads = 8 warps (2 M x 4 N); warp tile 64x32; mma m16n8k16.
// Stage = A 8KB + B 8KB = 16KB (64B rows, 4x16B chunks = k 0..31,
// swizzle c^((r>>1)&3)); 3 stages = 48KB static.

#define SWZ64(r, c) ((uint32_t)(r)*64u + ((uint32_t)(((c) ^ (((r)>>1)&3))) << 4))
#define B_OFF 8192
#define STG   16384

__device__ __forceinline__ void cp16(uint32_t d, const void* s) {
    asm volatile("cp.async.cg.shared.global [%0], [%1], 16;\n" :: "r"(d), "l"(s));
}
__device__ __forceinline__ void ldm4(uint32_t* r, uint32_t a) {
    asm volatile("ldmatrix.sync.aligned.m8n8.x4.shared.b16 {%0,%1,%2,%3}, [%4];\n"
        : "=r"(r[0]), "=r"(r[1]), "=r"(r[2]), "=r"(r[3]) : "r"(a));
}
__device__ __forceinline__ void mma16816(float* c, const uint32_t* a, uint32_t b0, uint32_t b1) {
    asm volatile("mma.sync.aligned.m16n8k16.row.col.f32.f16.f16.f32 "
        "{%0,%1,%2,%3}, {%4,%5,%6,%7}, {%8,%9}, {%0,%1,%2,%3};\n"
        : "+f"(c[0]), "+f"(c[1]), "+f"(c[2]), "+f"(c[3])
        : "r"(a[0]), "r"(a[1]), "r"(a[2]), "r"(a[3]), "r"(b0), "r"(b1));
}

// aptr/bptr: this thread's A/B row base pointers (row = tid>>1)
__device__ __forceinline__ void load_stage(uint32_t st,
    const __half* __restrict__ aptr, const __half* __restrict__ bptr,
    int k0, int tid)
{
    const int row = tid >> 1;
    const int c0  = (tid & 1) * 2;    // chunks c0, c0+1
    cp16(st +         SWZ64(row, c0),     aptr + k0 + c0*8);
    cp16(st +         SWZ64(row, c0 + 1), aptr + k0 + c0*8 + 8);
    cp16(st + B_OFF + SWZ64(row, c0),     bptr + k0 + c0*8);
    cp16(st + B_OFF + SWZ64(row, c0 + 1), bptr + k0 + c0*8 + 8);
}

__device__ __forceinline__ void gemm_mainloop(uint32_t sb,
    const __half* __restrict__ aptr, const __half* __restrict__ bptr,
    int K, int tid, int lane, int wm, int wn,
    float acc[4][4][4])
{
    const int nk = K / 32;   // >= 32 always

    load_stage(sb,       aptr, bptr, 0,  tid);
    asm volatile("cp.async.commit_group;\n");
    load_stage(sb + STG, aptr, bptr, 32, tid);
    asm volatile("cp.async.commit_group;\n");

    int s = 0;
    for (int kt = 0; kt < nk; kt++) {
        asm volatile("cp.async.wait_group 1;\n");
        __syncthreads();

        {
            int s2 = s + 2; if (s2 >= 3) s2 -= 3;
            if (kt + 2 < nk)
                load_stage(sb + s2*STG, aptr, bptr, (kt+2)*32, tid);
            asm volatile("cp.async.commit_group;\n");
        }

        const uint32_t Ab = sb + s*STG;

        #pragma unroll
        for (int kh = 0; kh < 2; kh++) {
            uint32_t fb[2][4];
            #pragma unroll
            for (int np = 0; np < 2; np++) {
                const int rb = wn*32 + np*16 + (lane & 7) + ((lane >> 4) << 3);
                const int cb = kh*2 + ((lane >> 3) & 1);
                ldm4(fb[np], Ab + B_OFF + SWZ64(rb, cb));
            }
            #pragma unroll
            for (int mt = 0; mt < 4; mt++) {
                uint32_t fa[4];
                const int ra = wm*64 + mt*16 + (lane & 15);
                const int ca = kh*2 + (lane >> 4);
                ldm4(fa, Ab + SWZ64(ra, ca));
                #pragma unroll
                for (int nt = 0; nt < 4; nt++) {
                    const int np = nt >> 1, hx = (nt & 1)*2;
                    mma16816(acc[mt][nt], fa, fb[np][hx], fb[np][hx+1]);
                }
            }
        }

        if (++s >= 3) s -= 3;
    }
    asm volatile("cp.async.wait_group 0;\n");
}

// ---------- merged gate_up GEMM with fused gather + SwiGLU epilogue ----------
// grid.x = 1792: [0,1280) routed (16 x-tiles, 80 y), [1280,1792) shared (32 x, 16 y)
// A rows read directly from x16 via rowtok (pads -> g_zero).
__global__ void __launch_bounds__(256, 2) gemm_gu_fused(
    const __half* __restrict__ x16, const __half* __restrict__ B_r,
    __half* __restrict__ C_r,
    const __half* __restrict__ B_s, __half* __restrict__ C_s,
    const int* __restrict__ tile_expert)
{
    __shared__ char smem[3*STG];   // 49152; reused as fp32 gate[128][65] in epilogue
    const uint32_t sb = smem_to_u32(smem);

    const int tid = threadIdx.x, lane = tid & 31, wid = tid >> 5;
    const int wm = wid & 1, wn = wid >> 1;
    const int row = tid >> 1;

    const __half *aptr, *bptr;
    __half *C;
    int m0, ldh, hcol0;
    bool routed;
    int bid = blockIdx.x;
    if (bid < 1280) {
        const int bx = bid & 15, by = bid >> 4;
        const int e = tile_expert[by];
        if (e < 0) return;
        m0 = by*128; hcol0 = bx*64;
        const int brow0 = e*(2*IDIM) + bx*128;
        const int tok = g_rowtok[m0 + row];
        aptr = (tok >= 0) ? (x16 + (size_t)tok*DIM) : g_zero;
        bptr = B_r + (size_t)(brow0 + row)*DIM;
        C = C_r; ldh = IDIM; routed = true;
    } else {
        bid -= 1280;
        const int bx = bid & 31, by = bid >> 5;
        m0 = by*128; hcol0 = bx*64;
        aptr = x16 + (size_t)(m0 + row)*DIM;
        bptr = B_s + (size_t)(bx*128 + row)*DIM;
        C = C_s; ldh = SIDIM; routed = false;
    }
    (void)routed;

    float acc[4][4][4];
    #pragma unroll
    for (int a = 0; a < 4; a++)
        #pragma unroll
        for (int b = 0; b < 4; b++)
            #pragma unroll
            for (int c = 0; c < 4; c++) acc[a][b][c] = 0.f;

    gemm_mainloop(sb, aptr, bptr, DIM, tid, lane, wm, wn, acc);

    // ---- fused SwiGLU epilogue ----
    float* gs = reinterpret_cast<float*>(smem);   // [128][65] fp32 = 33280 B
    __syncthreads();                               // smem repurpose barrier

    if (wn < 2) {
        // gate warps: tile cols 0..63 -> stage to smem
        #pragma unroll
        for (int mt = 0; mt < 4; mt++)
            #pragma unroll
            for (int nt = 0; nt < 4; nt++) {
                const int r = wm*64 + mt*16 + (lane >> 2);
                const int c = wn*32 + nt*8 + (lane & 3)*2;
                gs[r*65 + c]       = acc[mt][nt][0];
                gs[r*65 + c + 1]   = acc[mt][nt][1];
                gs[(r+8)*65 + c]   = acc[mt][nt][2];
                gs[(r+8)*65 + c+1] = acc[mt][nt][3];
            }
    }
    __syncthreads();

    if (wn >= 2) {
        // up warps: tile cols 64..127 -> h cols 0..63
        #pragma unroll
        for (int mt = 0; mt < 4; mt++)
            #pragma unroll
            for (int nt = 0; nt < 4; nt++) {
                const int r = wm*64 + mt*16 + (lane >> 2);
                const int j = (wn-2)*32 + nt*8 + (lane & 3)*2;
                #pragma unroll
                for (int half = 0; half < 2; half++) {
                    const int rr = r + half*8;
                    const float g0 = gs[rr*65 + j];
                    const float g1 = gs[rr*65 + j + 1];
                    const float u0 = acc[mt][nt][half*2];
                    const float u1 = acc[mt][nt][half*2 + 1];
                    const float h0 = (g0 / (1.f + expf(-g0))) * u0;
                    const float h1 = (g1 / (1.f + expf(-g1))) * u1;
                    union { __half b[2]; uint32_t u; } H;
                    H.b[0] = __float2half(h0);
                    H.b[1] = __float2half(h1);
                    const long long off = (long long)(m0 + rr)*ldh + hcol0 + j;
                    *reinterpret_cast<uint32_t*>(C + off) = H.u;
                }
            }
    }
}

// ---------- merged down GEMM (fp32 epilogue) ----------
// grid.x = 1536: [0,1280) routed (16 x, 80 y, K=IDIM), [1280,1536) shared (16 x, 16 y, K=SIDIM)
__global__ void __launch_bounds__(256, 2) gemm_down_merged(
    const __half* __restrict__ A_r, const __half* __restrict__ B_r,
    float* __restrict__ C_r,
    const __half* __restrict__ A_s, const __half* __restrict__ B_s,
    float* __restrict__ C_s,
    const int* __restrict__ tile_expert)
{
    __shared__ char smem[3*STG];
    const uint32_t sb = smem_to_u32(smem);

    const int tid = threadIdx.x, lane = tid & 31, wid = tid >> 5;
    const int wm = wid & 1, wn = wid >> 1;
    const int row = tid >> 1;

    const __half *aptr, *bptr;
    float* C;
    int m0, n0, K;
    int bid = blockIdx.x;
    if (bid < 1280) {
        const int bx = bid & 15, by = bid >> 4;
        const int e = tile_expert[by];
        if (e < 0) return;
        m0 = by*128; n0 = bx*128;
        K = IDIM;
        aptr = A_r + (size_t)(m0 + row)*K;
        bptr = B_r + (size_t)(e*DIM + n0 + row)*K;
        C = C_r;
    } else {
        bid -= 1280;
        const int bx = bid & 15, by = bid >> 4;
        m0 = by*128; n0 = bx*128;
        K = SIDIM;
        aptr = A_s + (size_t)(m0 + row)*K;
        bptr = B_s + (size_t)(n0 + row)*K;
        C = C_s;
    }

    float acc[4][4][4];
    #pragma unroll
    for (int a = 0; a < 4; a++)
        #pragma unroll
        for (int b = 0; b < 4; b++)
            #pragma unroll
            for (int c = 0; c < 4; c++) acc[a][b][c] = 0.f;

    gemm_mainloop(sb, aptr, bptr, K, tid, lane, wm, wn, acc);

    const int rbase = m0 + wm*64 + (lane >> 2);
    const int cbase = n0 + wn*32 + (lane & 3)*2;
    #pragma unroll
    for (int mt = 0; mt < 4; mt++)
        #pragma unroll
        for (int nt = 0; nt < 4; nt++) {
            const long long r0 = rbase + mt*16;
            const int c0 = cbase + nt*8;
            *reinterpret_cast<float2*>(C + r0*DIM + c0) =
                make_float2(acc[mt][nt][0], acc[mt][nt][1]);
            *reinterpret_cast<float2*>(C + (r0+8)*DIM + c0) =
                make_float2(acc[mt][nt][2], acc[mt][nt][3]);
        }
}

// ======================= combine =======================
__global__ void combine_kernel(float* __restrict__ out)
{
    const int t = blockIdx.x;
    __shared__ int   spos[TOPK];
    __shared__ float sw[TOPK];
    if (threadIdx.x < TOPK) {
        spos[threadIdx.x] = g_posmap[t*TOPK + threadIdx.x];
        sw[threadIdx.x]   = g_topw [t*TOPK + threadIdx.x];
    }
    __syncthreads();
    for (int d = threadIdx.x*4; d < DIM; d += blockDim.x*4) {
        float4 a = ld4(out + (long long)t*DIM + d);
        #pragma unroll
        for (int k = 0; k < TOPK; k++) {
            const float4 ev = ld4(g_eout + (long long)spos[k]*DIM + d);
            const float wk = sw[k];
            a.x = fmaf(wk, ev.x, a.x); a.y = fmaf(wk, ev.y, a.y);
            a.z = fmaf(wk, ev.z, a.z); a.w = fmaf(wk, ev.w, a.w);
        }
        *reinterpret_cast<float4*>(out + (long long)t*DIM + d) = a;
    }
}

// ======================= host =======================
extern "C" void kernel_launch(void* const* d_in, const int* in_sizes, int n_in,
                              void* d_out, int out_size)
{
    const float* x    = (const float*)d_in[0];
    const float* gw   = (const float*)d_in[1];
    const float* gb   = (const float*)d_in[2];
    const float* wgu  = (const float*)d_in[3];
    const float* wd   = (const float*)d_in[4];
    const float* wsgu = (const float*)d_in[5];
    const float* wsd  = (const float*)d_in[6];
    float* out = (float*)d_out;

    void *x16, *wguT, *wdT, *wsguT, *wsdT, *hb, *hsh, *eout, *tilee;
    cudaGetSymbolAddress(&x16, g_x16);
    cudaGetSymbolAddress(&wguT, g_wguT);   cudaGetSymbolAddress(&wdT, g_wdT);
    cudaGetSymbolAddress(&wsguT, g_wsguT); cudaGetSymbolAddress(&wsdT, g_wsdT);
    cudaGetSymbolAddress(&hb, g_hb);       cudaGetSymbolAddress(&hsh, g_hsh);
    cudaGetSymbolAddress(&eout, g_eout);
    cudaGetSymbolAddress(&tilee, g_tile_expert);

    // --- routing (+ x conversion fused into router) ---
    zero_meta<<<1, 32>>>();
    router_kernel<<<T_TOK, 512>>>(x, gw, gb, (__half*)x16);
    sched_kernel<<<1, 256>>>();
    scatter_kernel<<<(T_TOK*TOPK + 255)/256, 256>>>();

    // --- weight conversions ---
    transpose_convert<<<dim3(2*IDIM/32, DIM/32, NEXP), dim3(32,8)>>>(
        wgu, (__half*)wguT, DIM, 2*IDIM, IDIM);
    transpose_convert<<<dim3(DIM/32, IDIM/32, NEXP), dim3(32,8)>>>(
        wd, (__half*)wdT, IDIM, DIM, 0);
    transpose_convert<<<dim3(2*SIDIM/32, DIM/32, 1), dim3(32,8)>>>(
        wsgu, (__half*)wsguT, DIM, 2*SIDIM, SIDIM);
    transpose_convert<<<dim3(DIM/32, SIDIM/32, 1), dim3(32,8)>>>(
        wsd, (__half*)wsdT, SIDIM, DIM, 0);

    // --- merged gate_up GEMM + fused gather + SwiGLU (1280 routed + 512 shared) ---
    gemm_gu_fused<<<1792, 256>>>(
        (const __half*)x16, (const __half*)wguT, (__half*)hb,
        (const __half*)wsguT, (__half*)hsh,
        (const int*)tilee);

    // --- merged down GEMM (1280 routed + 256 shared) ---
    gemm_down_merged<<<1536, 256>>>(
        (const __half*)hb, (const __half*)wdT, (float*)eout,
        (const __half*)hsh, (const __half*)wsdT, out,
        (const int*)tilee);

    // --- combine ---
    combine_kernel<<<T_TOK, 256>>>(out);
}